// round 1
// baseline (speedup 1.0000x reference)
#include <cuda_runtime.h>

// ---------------- problem constants ----------------
#define BB 4
#define SS 2048
#define EE 1024
#define HH 16
#define DD 64
#define FF 4096
#define LN_EPS 1e-5f

// ---------------- scratch (device globals; no allocation allowed) ----------
__device__ float g_Q[(long)BB*HH*SS*DD];          // 8M floats
__device__ float g_K[(long)BB*HH*SS*DD];
__device__ float g_V[(long)BB*HH*SS*DD];
__device__ float g_scoresT[268435456];            // B*H*S*S = 1 GB (scores transposed: [b,h,t,s])
__device__ float g_attvec[(long)BB*SS*HH*DD];     // [B*S, H*D]
__device__ float g_y[(long)BB*SS*EE];             // WO out + residual (pre-LN)
__device__ float g_vatt[(long)BB*SS*EE];          // vector_att
__device__ float g_ffn1[(long)BB*SS*FF];          // 128 MB
__device__ float g_z[(long)BB*SS*EE];             // FFN out + residual (pre-LN)

// ---------------- generic tiled fp32 GEMM ----------------
// C[m,n] = sum_k Alog[m,k] * Blog[k,n]  (+bias[n]) (+residual[m,n]) (relu)
// TA: Alog[m,k] = A[k*lda + m]   (physical K x M)
// TB: Blog[k,n] = B[n*ldb + k]   (physical N x K)
// batch: z = z1*Z2 + z2, pointer offsets per (z1, z2).
#define GBM 64
#define GBN 64
#define GBK 16

template<bool TA, bool TB>
__global__ __launch_bounds__(256)
void gemm_kernel(const float* __restrict__ A, const float* __restrict__ B,
                 float* __restrict__ C,
                 int M, int N, int K, int lda, int ldb, int ldc,
                 long sA1, long sA2, long sB1, long sB2, long sC1, long sC2, int Z2,
                 const float* __restrict__ bias,
                 const float* __restrict__ residual, int ldr,
                 int do_relu)
{
    int z  = blockIdx.z;
    int z1 = z / Z2, z2 = z - z1 * Z2;
    A += z1 * sA1 + z2 * sA2;
    B += z1 * sB1 + z2 * sB2;
    C += z1 * sC1 + z2 * sC2;

    __shared__ float As[GBK][GBM + 4];
    __shared__ float Bs[GBK][GBN + 4];

    const int tid = threadIdx.x;        // 0..255
    const int tx  = tid & 15;
    const int ty  = tid >> 4;
    const int m0  = blockIdx.y * GBM;
    const int n0  = blockIdx.x * GBN;

    float acc[4][4] = {};

    for (int k0 = 0; k0 < K; k0 += GBK) {
        // ---- load A tile (64 x 16 logical) ----
        if (!TA) {
            int r = tid >> 2;            // 0..63 (m)
            int c = (tid & 3) * 4;       // 0..12 (k)
            float4 v = *reinterpret_cast<const float4*>(&A[(long)(m0 + r) * lda + (k0 + c)]);
            As[c + 0][r] = v.x; As[c + 1][r] = v.y; As[c + 2][r] = v.z; As[c + 3][r] = v.w;
        } else {
            int c = tid >> 4;            // 0..15 (k)
            int r = (tid & 15) * 4;      // 0..60 (m)
            float4 v = *reinterpret_cast<const float4*>(&A[(long)(k0 + c) * lda + (m0 + r)]);
            As[c][r + 0] = v.x; As[c][r + 1] = v.y; As[c][r + 2] = v.z; As[c][r + 3] = v.w;
        }
        // ---- load B tile (16 x 64 logical) ----
        if (!TB) {
            int c = tid >> 4;            // 0..15 (k)
            int n = (tid & 15) * 4;      // 0..60 (n)
            float4 v = *reinterpret_cast<const float4*>(&B[(long)(k0 + c) * ldb + (n0 + n)]);
            Bs[c][n + 0] = v.x; Bs[c][n + 1] = v.y; Bs[c][n + 2] = v.z; Bs[c][n + 3] = v.w;
        } else {
            int n = tid >> 2;            // 0..63 (n)
            int c = (tid & 3) * 4;       // 0..12 (k)
            float4 v = *reinterpret_cast<const float4*>(&B[(long)(n0 + n) * ldb + (k0 + c)]);
            Bs[c + 0][n] = v.x; Bs[c + 1][n] = v.y; Bs[c + 2][n] = v.z; Bs[c + 3][n] = v.w;
        }
        __syncthreads();

        #pragma unroll
        for (int kk = 0; kk < GBK; kk++) {
            float ra[4], rb[4];
            #pragma unroll
            for (int i = 0; i < 4; i++) ra[i] = As[kk][ty * 4 + i];
            #pragma unroll
            for (int j = 0; j < 4; j++) rb[j] = Bs[kk][tx * 4 + j];
            #pragma unroll
            for (int i = 0; i < 4; i++)
                #pragma unroll
                for (int j = 0; j < 4; j++)
                    acc[i][j] += ra[i] * rb[j];
        }
        __syncthreads();
    }

    #pragma unroll
    for (int i = 0; i < 4; i++) {
        int m = m0 + ty * 4 + i;
        #pragma unroll
        for (int j = 0; j < 4; j++) {
            int n = n0 + tx * 4 + j;
            float v = acc[i][j];
            if (bias)     v += bias[n];
            if (residual) v += residual[(long)m * ldr + n];
            if (do_relu)  v = fmaxf(v, 0.0f);
            C[(long)m * ldc + n] = v;
        }
    }
}

// ---------------- softmax over last axis of scoresT rows, then * 1/sqrt(D) ----
// one block of 256 threads per row of length SS=2048 (8 values/thread, register-resident)
__global__ __launch_bounds__(256)
void softmax_kernel(float* __restrict__ sc)
{
    const int S = SS;
    long row = blockIdx.x;
    float* p = sc + row * (long)S;
    const int tid  = threadIdx.x;
    const int lane = tid & 31;
    const int warp = tid >> 5;

    float v[8];
    float m = -1e30f;
    #pragma unroll
    for (int i = 0; i < 8; i++) { v[i] = p[tid + i * 256]; m = fmaxf(m, v[i]); }

    __shared__ float redm[8];
    __shared__ float reds[8];
    #pragma unroll
    for (int o = 16; o > 0; o >>= 1) m = fmaxf(m, __shfl_xor_sync(0xffffffffu, m, o));
    if (lane == 0) redm[warp] = m;
    __syncthreads();
    float bm = redm[0];
    #pragma unroll
    for (int i = 1; i < 8; i++) bm = fmaxf(bm, redm[i]);

    float s = 0.0f;
    #pragma unroll
    for (int i = 0; i < 8; i++) { v[i] = __expf(v[i] - bm); s += v[i]; }
    #pragma unroll
    for (int o = 16; o > 0; o >>= 1) s += __shfl_xor_sync(0xffffffffu, s, o);
    if (lane == 0) reds[warp] = s;
    __syncthreads();
    float bs = reds[0];
    #pragma unroll
    for (int i = 1; i < 8; i++) bs += reds[i];

    float inv = 0.125f / bs;   // 1/sqrt(64) applied AFTER softmax (faithful quirk)
    #pragma unroll
    for (int i = 0; i < 8; i++) p[tid + i * 256] = v[i] * inv;
}

// ---------------- layernorm over last axis (E=1024), block per row -------
__global__ __launch_bounds__(256)
void layernorm_kernel(const float* __restrict__ x,
                      const float* __restrict__ gamma,
                      const float* __restrict__ beta,
                      float* __restrict__ out)
{
    const int E = EE;
    long row = blockIdx.x;
    const float* p = x + row * (long)E;
    float* o = out + row * (long)E;
    const int tid  = threadIdx.x;
    const int lane = tid & 31;
    const int warp = tid >> 5;

    float v[4];
    float s = 0.0f;
    #pragma unroll
    for (int i = 0; i < 4; i++) { v[i] = p[tid + i * 256]; s += v[i]; }

    __shared__ float red1[8];
    __shared__ float red2[8];
    #pragma unroll
    for (int off = 16; off > 0; off >>= 1) s += __shfl_xor_sync(0xffffffffu, s, off);
    if (lane == 0) red1[warp] = s;
    __syncthreads();
    float tot = red1[0];
    #pragma unroll
    for (int i = 1; i < 8; i++) tot += red1[i];
    float mu = tot * (1.0f / E);

    float q = 0.0f;
    #pragma unroll
    for (int i = 0; i < 4; i++) { float d = v[i] - mu; q += d * d; }
    #pragma unroll
    for (int off = 16; off > 0; off >>= 1) q += __shfl_xor_sync(0xffffffffu, q, off);
    if (lane == 0) red2[warp] = q;
    __syncthreads();
    float qt = red2[0];
    #pragma unroll
    for (int i = 1; i < 8; i++) qt += red2[i];
    float rstd = rsqrtf(qt * (1.0f / E) + LN_EPS);

    #pragma unroll
    for (int i = 0; i < 4; i++) {
        int col = tid + i * 256;
        o[col] = (v[i] - mu) * rstd * gamma[col] + beta[col];
    }
}

// ---------------- launcher ----------------
extern "C" void kernel_launch(void* const* d_in, const int* in_sizes, int n_in,
                              void* d_out, int out_size)
{
    const float* X     = (const float*)d_in[0];
    const float* WQ    = (const float*)d_in[1];
    const float* WK    = (const float*)d_in[2];
    const float* WV    = (const float*)d_in[3];
    const float* WO    = (const float*)d_in[4];
    const float* gamma = (const float*)d_in[5];
    const float* beta  = (const float*)d_in[6];
    const float* W1    = (const float*)d_in[7];
    const float* b1    = (const float*)d_in[8];
    const float* W2    = (const float*)d_in[9];
    const float* b2    = (const float*)d_in[10];
    float* out = (float*)d_out;

    float *Q, *K, *V, *SC, *AV, *Y, *VA, *H1, *Z;
    cudaGetSymbolAddress((void**)&Q,  g_Q);
    cudaGetSymbolAddress((void**)&K,  g_K);
    cudaGetSymbolAddress((void**)&V,  g_V);
    cudaGetSymbolAddress((void**)&SC, g_scoresT);
    cudaGetSymbolAddress((void**)&AV, g_attvec);
    cudaGetSymbolAddress((void**)&Y,  g_y);
    cudaGetSymbolAddress((void**)&VA, g_vatt);
    cudaGetSymbolAddress((void**)&H1, g_ffn1);
    cudaGetSymbolAddress((void**)&Z,  g_z);

    const long SD  = (long)SS * DD;
    const long SE  = (long)SS * EE;
    const long ED  = (long)EE * DD;
    const long SSS = (long)SS * SS;
    const long SHD = (long)SS * HH * DD;

    dim3 blk(256);

    // 1) Q/K/V projections: per (b,h): [S,E] @ [E,D] -> [B,H,S,D]
    {
        dim3 grid(DD / GBN, SS / GBM, BB * HH);
        gemm_kernel<false, false><<<grid, blk>>>(X, WQ, Q,
            SS, DD, EE, EE, DD, DD,
            SE, 0, 0, ED, (long)HH * SD, SD, HH,
            nullptr, nullptr, 0, 0);
        gemm_kernel<false, false><<<grid, blk>>>(X, WK, K,
            SS, DD, EE, EE, DD, DD,
            SE, 0, 0, ED, (long)HH * SD, SD, HH,
            nullptr, nullptr, 0, 0);
        gemm_kernel<false, false><<<grid, blk>>>(X, WV, V,
            SS, DD, EE, EE, DD, DD,
            SE, 0, 0, ED, (long)HH * SD, SD, HH,
            nullptr, nullptr, 0, 0);
    }

    // 2) scoresT[b,h,t,s] = sum_d K[t,d] * Q[s,d]   (NT GEMM, per (b,h))
    {
        dim3 grid(SS / GBN, SS / GBM, BB * HH);
        gemm_kernel<false, true><<<grid, blk>>>(K, Q, SC,
            SS, SS, DD, DD, DD, SS,
            (long)HH * SD, SD, (long)HH * SD, SD, (long)HH * SSS, SSS, HH,
            nullptr, nullptr, 0, 0);
    }

    // 3) softmax over s (last axis of scoresT rows) then * 1/sqrt(D)
    softmax_kernel<<<(long)BB * HH * SS, blk>>>(SC);

    // 4) att_vec[b,s, h*D+d] = sum_t attT[t,s] * V[t,d]   (TN GEMM, per (b,h))
    {
        dim3 grid(DD / GBN, SS / GBM, BB * HH);
        gemm_kernel<true, false><<<grid, blk>>>(SC, V, AV,
            SS, DD, SS, SS, DD, HH * DD,
            (long)HH * SSS, SSS, (long)HH * SD, SD, SHD, (long)DD, HH,
            nullptr, nullptr, 0, 0);
    }

    // 5) Y = att_vec @ WO + X   (then LN -> vector_att)
    {
        dim3 grid(EE / GBN, (BB * SS) / GBM, 1);
        gemm_kernel<false, false><<<grid, blk>>>(AV, WO, Y,
            BB * SS, EE, HH * DD, HH * DD, EE, EE,
            0, 0, 0, 0, 0, 0, 1,
            nullptr, X, EE, 0);
    }
    layernorm_kernel<<<BB * SS, blk>>>(Y, gamma, beta, VA);

    // 6) H1 = relu(vector_att @ W1 + b1)
    {
        dim3 grid(FF / GBN, (BB * SS) / GBM, 1);
        gemm_kernel<false, false><<<grid, blk>>>(VA, W1, H1,
            BB * SS, FF, EE, EE, FF, FF,
            0, 0, 0, 0, 0, 0, 1,
            b1, nullptr, 0, 1);
    }

    // 7) Z = H1 @ W2 + b2 + vector_att   (then LN -> out)
    {
        dim3 grid(EE / GBN, (BB * SS) / GBM, 1);
        gemm_kernel<false, false><<<grid, blk>>>(H1, W2, Z,
            BB * SS, EE, FF, FF, EE, EE,
            0, 0, 0, 0, 0, 0, 1,
            b2, VA, EE, 0);
    }
    layernorm_kernel<<<BB * SS, blk>>>(Z, gamma, beta, out);
}

// round 4
// speedup vs baseline: 4.1788x; 4.1788x over previous
#include <cuda_runtime.h>
#include <cuda_fp16.h>
#include <cstdint>

#define BB 4
#define SS 2048
#define EE 1024
#define HH 16
#define DD 64
#define FF 4096
#define LN_EPS 1e-5f
#define NTOK (BB*SS)

// ---------------- scratch (device globals) ----------------
__device__ __half g_Xh[(long)NTOK*EE];
__device__ __half g_Wqk[2048L*EE];          // rows: [Q(h*64+d) | K(h*64+d)], cols e
__device__ __half g_Wvt[1024L*EE];          // rows h*64+d, cols e
__device__ __half g_Wot[1024L*1024];        // rows e_out, cols hd
__device__ __half g_W1t[(long)FF*EE];       // rows f, cols e
__device__ __half g_W2t[(long)EE*FF];       // rows e, cols f
__device__ __half g_QKh[(long)NTOK*2048];   // [b*S+s][ Q: h*64+d , K: 1024+h*64+d ]
__device__ __half g_Vth[(long)BB*1024*SS];  // [b][h*64+d][t]
__device__ float  g_scores[268435456L];     // [b,h][s][t]  (1 GB)
__device__ __half g_att[268435456L];        // [b,h][s][t]  (0.5 GB)
__device__ __half g_AVh[(long)NTOK*EE];     // [b*S+s][h*64+d]
__device__ float  g_Y[(long)NTOK*EE];
__device__ float  g_VAf[(long)NTOK*EE];
__device__ __half g_VAh[(long)NTOK*EE];
__device__ __half g_H1h[(long)NTOK*FF];
__device__ float  g_Z[(long)NTOK*EE];

// ---------------- PTX helpers ----------------
__device__ __forceinline__ uint32_t smem_u32(const void* p) {
    uint32_t a;
    asm("{ .reg .u64 t; cvta.to.shared.u64 t, %1; cvt.u32.u64 %0, t; }" : "=r"(a) : "l"(p));
    return a;
}
__device__ __forceinline__ void cp16(uint32_t dst, const void* src) {
    asm volatile("cp.async.cg.shared.global [%0], [%1], 16;" :: "r"(dst), "l"(src));
}

// ---------------- HMMA f16 GEMM: C[M,N] = A[M,K] * B[N,K]^T ----------------
// A, B half, K-major (K contiguous). BM=128 fixed, BK=64. K % 64 == 0.
// 256 threads = 8 warps (4 m x 2 n). Warp tile: 32 x (BN/2).
template<int BN, bool OUT_HALF>
__global__ __launch_bounds__(256)
void hgemm_kernel(const __half* __restrict__ A, const __half* __restrict__ B,
                  void* __restrict__ Cv, int K, int lda, int ldb, int ldc,
                  long sA1, long sA2, long sB1, long sB2, long sC1, long sC2, int Z2,
                  const float* __restrict__ bias, const float* __restrict__ residual,
                  int ldr, int do_relu)
{
    constexpr int BM = 128;
    constexpr int STG_A = BM * 128;       // bytes per A stage (128B = 64 halfs per row)
    constexpr int STG_B = BN * 128;
    constexpr int STG   = STG_A + STG_B;
    constexpr int WN = BN / 2;            // warp n extent
    constexpr int NT = WN / 8;            // n-tiles (m16n8k16) per warp

    extern __shared__ char smem_raw[];
    const uint32_t sb0   = smem_u32(smem_raw);
    const uint32_t sbase = (sb0 + 127u) & ~127u;

    const int tid  = threadIdx.x;
    const int lane = tid & 31;
    const int wid  = tid >> 5;
    const int wm   = (wid & 3) << 5;      // warp m offset (0,32,64,96)
    const int wn   = (wid >> 2) * WN;     // warp n offset

    const int z  = blockIdx.z;
    const int z1 = z / Z2, z2 = z - z1 * Z2;
    A += z1 * sA1 + z2 * sA2;
    B += z1 * sB1 + z2 * sB2;
    const long coff = z1 * sC1 + z2 * sC2;
    const int m0 = blockIdx.y * BM;
    const int n0 = blockIdx.x * BN;

    float acc[2][NT][4];
    #pragma unroll
    for (int i = 0; i < 2; i++)
        #pragma unroll
        for (int j = 0; j < NT; j++)
            #pragma unroll
            for (int k = 0; k < 4; k++) acc[i][j][k] = 0.0f;

    const int nK = K >> 6;

    auto load_stage = [&](int stg, int kt) {
        uint32_t sA = sbase + stg * STG;
        const char* Ab = (const char*)(A + (long)m0 * lda + kt * 64);
        #pragma unroll
        for (int idx = tid; idx < BM * 8; idx += 256) {
            int r = idx >> 3, c = (idx & 7) << 4;
            uint32_t off = (uint32_t)(r * 128 + c); off ^= (off >> 3) & 0x70;
            cp16(sA + off, Ab + (long)r * lda * 2 + c);
        }
        uint32_t sB = sbase + stg * STG + STG_A;
        const char* Bb = (const char*)(B + (long)n0 * ldb + kt * 64);
        #pragma unroll
        for (int idx = tid; idx < BN * 8; idx += 256) {
            int r = idx >> 3, c = (idx & 7) << 4;
            uint32_t off = (uint32_t)(r * 128 + c); off ^= (off >> 3) & 0x70;
            cp16(sB + off, Bb + (long)r * ldb * 2 + c);
        }
        asm volatile("cp.async.commit_group;" ::: "memory");
    };

    load_stage(0, 0);

    for (int i = 0; i < nK; i++) {
        const int cur = i & 1;
        if (i + 1 < nK) {
            load_stage(1 - cur, i + 1);
            asm volatile("cp.async.wait_group 1;" ::: "memory");
        } else {
            asm volatile("cp.async.wait_group 0;" ::: "memory");
        }
        __syncthreads();

        const uint32_t sA = sbase + cur * STG;
        const uint32_t sB = sA + STG_A;
        #pragma unroll
        for (int ks = 0; ks < 4; ks++) {
            uint32_t a[2][4];
            #pragma unroll
            for (int mt = 0; mt < 2; mt++) {
                int m = wm + (mt << 4) + (lane & 15);
                uint32_t off = (uint32_t)((m << 7) + (ks << 5) + ((lane >> 4) << 4));
                off ^= (off >> 3) & 0x70;
                asm volatile("ldmatrix.sync.aligned.m8n8.x4.shared.b16 {%0,%1,%2,%3}, [%4];"
                    : "=r"(a[mt][0]), "=r"(a[mt][1]), "=r"(a[mt][2]), "=r"(a[mt][3])
                    : "r"(sA + off));
            }
            uint32_t b[NT][2];
            #pragma unroll
            for (int p = 0; p < NT / 2; p++) {
                int quad = lane >> 3;
                int n = wn + (p << 4) + ((quad & 2) << 2) + (lane & 7);
                uint32_t off = (uint32_t)((n << 7) + (ks << 5) + ((quad & 1) << 4));
                off ^= (off >> 3) & 0x70;
                asm volatile("ldmatrix.sync.aligned.m8n8.x4.shared.b16 {%0,%1,%2,%3}, [%4];"
                    : "=r"(b[2*p][0]), "=r"(b[2*p][1]), "=r"(b[2*p+1][0]), "=r"(b[2*p+1][1])
                    : "r"(sB + off));
            }
            #pragma unroll
            for (int mt = 0; mt < 2; mt++)
                #pragma unroll
                for (int nt = 0; nt < NT; nt++)
                    asm volatile("mma.sync.aligned.m16n8k16.row.col.f32.f16.f16.f32 "
                        "{%0,%1,%2,%3}, {%4,%5,%6,%7}, {%8,%9}, {%0,%1,%2,%3};"
                        : "+f"(acc[mt][nt][0]), "+f"(acc[mt][nt][1]),
                          "+f"(acc[mt][nt][2]), "+f"(acc[mt][nt][3])
                        : "r"(a[mt][0]), "r"(a[mt][1]), "r"(a[mt][2]), "r"(a[mt][3]),
                          "r"(b[nt][0]), "r"(b[nt][1]));
        }
        __syncthreads();
    }

    // -------- epilogue: register fragments -> global (fused bias/residual/relu) ----
    const int mrow = lane >> 2;
    const int ncol = (lane & 3) << 1;
    #pragma unroll
    for (int mt = 0; mt < 2; mt++) {
        #pragma unroll
        for (int nt = 0; nt < NT; nt++) {
            long gm = m0 + wm + (mt << 4) + mrow;
            int  gn = n0 + wn + (nt << 3) + ncol;
            float v0 = acc[mt][nt][0], v1 = acc[mt][nt][1];
            float v2 = acc[mt][nt][2], v3 = acc[mt][nt][3];
            if (bias) {
                float b0 = bias[gn], b1 = bias[gn + 1];
                v0 += b0; v1 += b1; v2 += b0; v3 += b1;
            }
            if (residual) {
                v0 += residual[gm * ldr + gn];       v1 += residual[gm * ldr + gn + 1];
                v2 += residual[(gm + 8) * ldr + gn]; v3 += residual[(gm + 8) * ldr + gn + 1];
            }
            if (do_relu) {
                v0 = fmaxf(v0, 0.0f); v1 = fmaxf(v1, 0.0f);
                v2 = fmaxf(v2, 0.0f); v3 = fmaxf(v3, 0.0f);
            }
            if (OUT_HALF) {
                *(__half2*)((__half*)Cv + coff + gm * ldc + gn)       = __floats2half2_rn(v0, v1);
                *(__half2*)((__half*)Cv + coff + (gm + 8) * ldc + gn) = __floats2half2_rn(v2, v3);
            } else {
                float* p0 = (float*)Cv + coff + gm * ldc + gn;
                p0[0] = v0; p0[1] = v1;
                float* p1 = (float*)Cv + coff + (gm + 8) * ldc + gn;
                p1[0] = v2; p1[1] = v3;
            }
        }
    }
}

// ---------------- conversion / packing kernels ----------------
__global__ __launch_bounds__(256) void f2h_kernel(const float* __restrict__ s,
                                                  __half* __restrict__ d, long n) {
    long i = (long)blockIdx.x * 256 + threadIdx.x;
    if (i < n) d[i] = __float2half(s[i]);
}
__global__ __launch_bounds__(256) void pack_qk_kernel(const float* __restrict__ WQ,
                                                      const float* __restrict__ WK,
                                                      __half* __restrict__ dst) {
    long i = (long)blockIdx.x * 256 + threadIdx.x;   // over 2048*1024
    int n = (int)(i >> 10), e = (int)(i & 1023);
    const float* W = (n < 1024) ? WQ : WK;
    int hd = n & 1023; int h = hd >> 6, d = hd & 63;
    dst[i] = __float2half(W[((long)h * 1024 + e) * 64 + d]);
}
__global__ __launch_bounds__(256) void pack_vt_kernel(const float* __restrict__ WV,
                                                      __half* __restrict__ dst) {
    long i = (long)blockIdx.x * 256 + threadIdx.x;   // over 1024*1024
    int n = (int)(i >> 10), e = (int)(i & 1023);
    int h = n >> 6, d = n & 63;
    dst[i] = __float2half(WV[((long)h * 1024 + e) * 64 + d]);
}
__global__ __launch_bounds__(256) void transpose_h_kernel(const float* __restrict__ src,
                                                          __half* __restrict__ dst,
                                                          int R, int C) {
    long i = (long)blockIdx.x * 256 + threadIdx.x;   // i = c*R + r
    if (i >= (long)R * C) return;
    int c = (int)(i / R), r = (int)(i % R);
    dst[i] = __float2half(src[(long)r * C + c]);
}

// ---------------- column softmax over s (query axis) ----------------
__global__ __launch_bounds__(256) void softmax_col_kernel(const float* __restrict__ sc,
                                                          __half* __restrict__ att) {
    long z = blockIdx.y;
    int  t = blockIdx.x * 256 + threadIdx.x;
    const float* p = sc + z * (long)SS * SS + t;
    __half* o = att + z * (long)SS * SS + t;
    float sum = 0.0f;
    for (int s = 0; s < SS; s++) sum += __expf(p[(long)s * SS] - 20.0f);
    float inv = 0.125f / sum;
    for (int s = 0; s < SS; s++)
        o[(long)s * SS] = __float2half(__expf(p[(long)s * SS] - 20.0f) * inv);
}

// ---------------- layernorm (E=1024), optional half copy ----------------
__global__ __launch_bounds__(256)
void layernorm_kernel(const float* __restrict__ x, const float* __restrict__ gamma,
                      const float* __restrict__ beta, float* __restrict__ outf,
                      __half* __restrict__ outh) {
    long row = blockIdx.x;
    const float* p = x + row * (long)EE;
    const int tid = threadIdx.x, lane = tid & 31, warp = tid >> 5;

    float v[4]; float s = 0.0f;
    #pragma unroll
    for (int i = 0; i < 4; i++) { v[i] = p[tid + i * 256]; s += v[i]; }
    __shared__ float red1[8], red2[8];
    #pragma unroll
    for (int o = 16; o > 0; o >>= 1) s += __shfl_xor_sync(0xffffffffu, s, o);
    if (lane == 0) red1[warp] = s;
    __syncthreads();
    float tot = red1[0];
    #pragma unroll
    for (int i = 1; i < 8; i++) tot += red1[i];
    float mu = tot * (1.0f / EE);

    float q = 0.0f;
    #pragma unroll
    for (int i = 0; i < 4; i++) { float d = v[i] - mu; q += d * d; }
    #pragma unroll
    for (int o = 16; o > 0; o >>= 1) q += __shfl_xor_sync(0xffffffffu, q, o);
    if (lane == 0) red2[warp] = q;
    __syncthreads();
    float qt = red2[0];
    #pragma unroll
    for (int i = 1; i < 8; i++) qt += red2[i];
    float rstd = rsqrtf(qt * (1.0f / EE) + LN_EPS);

    #pragma unroll
    for (int i = 0; i < 4; i++) {
        int col = tid + i * 256;
        float y = (v[i] - mu) * rstd * gamma[col] + beta[col];
        outf[row * (long)EE + col] = y;
        if (outh) outh[row * (long)EE + col] = __float2half(y);
    }
}

// ---------------- launcher ----------------
extern "C" void kernel_launch(void* const* d_in, const int* in_sizes, int n_in,
                              void* d_out, int out_size)
{
    const float* X     = (const float*)d_in[0];
    const float* WQ    = (const float*)d_in[1];
    const float* WK    = (const float*)d_in[2];
    const float* WV    = (const float*)d_in[3];
    const float* WO    = (const float*)d_in[4];
    const float* gamma = (const float*)d_in[5];
    const float* beta  = (const float*)d_in[6];
    const float* W1    = (const float*)d_in[7];
    const float* b1    = (const float*)d_in[8];
    const float* W2    = (const float*)d_in[9];
    const float* b2    = (const float*)d_in[10];
    float* out = (float*)d_out;

    __half *Xh, *Wqk, *Wvt, *Wot, *W1t, *W2t, *QKh, *Vth, *ATT, *AVh, *VAh, *H1h;
    float *SC, *Y, *VAf, *Z;
    cudaGetSymbolAddress((void**)&Xh,  g_Xh);
    cudaGetSymbolAddress((void**)&Wqk, g_Wqk);
    cudaGetSymbolAddress((void**)&Wvt, g_Wvt);
    cudaGetSymbolAddress((void**)&Wot, g_Wot);
    cudaGetSymbolAddress((void**)&W1t, g_W1t);
    cudaGetSymbolAddress((void**)&W2t, g_W2t);
    cudaGetSymbolAddress((void**)&QKh, g_QKh);
    cudaGetSymbolAddress((void**)&Vth, g_Vth);
    cudaGetSymbolAddress((void**)&SC,  g_scores);
    cudaGetSymbolAddress((void**)&ATT, g_att);
    cudaGetSymbolAddress((void**)&AVh, g_AVh);
    cudaGetSymbolAddress((void**)&Y,   g_Y);
    cudaGetSymbolAddress((void**)&VAf, g_VAf);
    cudaGetSymbolAddress((void**)&VAh, g_VAh);
    cudaGetSymbolAddress((void**)&H1h, g_H1h);
    cudaGetSymbolAddress((void**)&Z,   g_Z);

    const int SM128 = 2 * (128 * 128 + 128 * 128) + 256;   // 65792 bytes
    const int SM64  = 2 * (128 * 128 +  64 * 128) + 256;   // 49408 bytes
    cudaFuncSetAttribute(hgemm_kernel<128, true>,  cudaFuncAttributeMaxDynamicSharedMemorySize, SM128);
    cudaFuncSetAttribute(hgemm_kernel<128, false>, cudaFuncAttributeMaxDynamicSharedMemorySize, SM128);
    cudaFuncSetAttribute(hgemm_kernel<64,  true>,  cudaFuncAttributeMaxDynamicSharedMemorySize, SM64);

    const long SSl = SS, SSS = SSl * SSl;
    dim3 blk(256);

    // 0) conversions / packing
    f2h_kernel<<<(NTOK * (long)EE) / 256, blk>>>(X, Xh, (long)NTOK * EE);
    pack_qk_kernel<<<(2048L * EE) / 256, blk>>>(WQ, WK, Wqk);
    pack_vt_kernel<<<(1024L * EE) / 256, blk>>>(WV, Wvt);
    transpose_h_kernel<<<(1024L * 1024) / 256, blk>>>(WO, Wot, 1024, 1024);
    transpose_h_kernel<<<((long)EE * FF) / 256, blk>>>(W1, W1t, EE, FF);   // dst [F][E]
    transpose_h_kernel<<<((long)FF * EE) / 256, blk>>>(W2, W2t, FF, EE);   // dst [E][F]

    // 1) QK projection: [8192,1024] x [2048,1024]^T -> QKh [8192,2048] half
    hgemm_kernel<128, true><<<dim3(2048 / 128, NTOK / 128, 1), blk, SM128>>>(
        Xh, Wqk, QKh, EE, EE, EE, 2048,
        0, 0, 0, 0, 0, 0, 1, nullptr, nullptr, 0, 0);

    // 2) Vt: per b: [1024,1024](Wvt) x [2048,1024](Xh_b)^T -> Vth[b][1024,2048] half
    hgemm_kernel<128, true><<<dim3(SS / 128, 1024 / 128, BB), blk, SM128>>>(
        Wvt, Xh, Vth, EE, EE, EE, SS,
        0, 0, (long)SS * EE, 0, 1024L * SS, 0, 1, nullptr, nullptr, 0, 0);

    // 3) scores: per (b,h): Q[2048,64] x K[2048,64]^T -> fp32 [s,t]
    hgemm_kernel<128, false><<<dim3(SS / 128, SS / 128, BB * HH), blk, SM128>>>(
        QKh, QKh + 1024, SC, DD, 2048, 2048, SS,
        SSl * 2048, 64, SSl * 2048, 64, (long)HH * SSS, SSS, HH,
        nullptr, nullptr, 0, 0);

    // 4) column softmax (query axis) -> att half
    softmax_col_kernel<<<dim3(SS / 256, BB * HH), blk>>>(SC, ATT);

    // 5) AV: per (b,h): att[2048,2048] x Vt[64,2048]^T -> AVh[b*S+s][h*64+d]
    hgemm_kernel<64, true><<<dim3(1, SS / 128, BB * HH), blk, SM64>>>(
        ATT, Vth, AVh, SS, SS, SS, EE,
        (long)HH * SSS, SSS, 1024L * SS, 64L * SS, SSl * EE, 64, HH,
        nullptr, nullptr, 0, 0);

    // 6) WO: [8192,1024] x [1024,1024]^T + X -> Y fp32; LN -> VAf/VAh
    hgemm_kernel<128, false><<<dim3(EE / 128, NTOK / 128, 1), blk, SM128>>>(
        AVh, Wot, Y, 1024, 1024, 1024, EE,
        0, 0, 0, 0, 0, 0, 1, nullptr, X, EE, 0);
    layernorm_kernel<<<NTOK, blk>>>(Y, gamma, beta, VAf, VAh);

    // 7) FFN1: [8192,1024] x [4096,1024]^T + b1, relu -> H1h half
    hgemm_kernel<128, true><<<dim3(FF / 128, NTOK / 128, 1), blk, SM128>>>(
        VAh, W1t, H1h, EE, EE, EE, FF,
        0, 0, 0, 0, 0, 0, 1, b1, nullptr, 0, 1);

    // 8) FFN2: [8192,4096] x [1024,4096]^T + b2 + VAf -> Z fp32; LN -> out
    hgemm_kernel<128, false><<<dim3(EE / 128, NTOK / 128, 1), blk, SM128>>>(
        H1h, W2t, Z, FF, FF, FF, EE,
        0, 0, 0, 0, 0, 0, 1, b2, VAf, EE, 0);
    layernorm_kernel<<<NTOK, blk>>>(Z, gamma, beta, out, nullptr);
}

// round 5
// speedup vs baseline: 4.8673x; 1.1648x over previous
#include <cuda_runtime.h>
#include <cuda_fp16.h>
#include <cstdint>

#define BB 4
#define SS 2048
#define EE 1024
#define HH 16
#define DD 64
#define FF 4096
#define LN_EPS 1e-5f
#define NTOK (BB*SS)
#define EXP_SHIFT 12.0f

// ---------------- scratch (device globals) ----------------
__device__ __half g_Xh[(long)NTOK*EE];
__device__ __half g_Wqk[2048L*EE];          // rows: [Q(h*64+d) | K(h*64+d)], cols e
__device__ __half g_Wvt[1024L*EE];          // rows h*64+d, cols e
__device__ __half g_Wot[1024L*1024];        // rows e_out, cols hd
__device__ __half g_W1t[(long)FF*EE];       // rows f, cols e
__device__ __half g_W2t[(long)EE*FF];       // rows e, cols f
__device__ __half g_QKh[(long)NTOK*2048];   // [b*S+s][ Q: h*64+d , K: 1024+h*64+d ]
__device__ __half g_Vth[(long)BB*1024*SS];  // [b][h*64+d][t]
__device__ __half g_att[268435456L];        // [b,h][s][t]  unnormalized exp (0.5 GB)
__device__ float  g_inv[(long)BB*HH*SS];    // 0.125 / colsum per (z,t)
__device__ __half g_AVh[(long)NTOK*EE];     // [b*S+s][h*64+d]
__device__ float  g_Y[(long)NTOK*EE];
__device__ float  g_VAf[(long)NTOK*EE];
__device__ __half g_VAh[(long)NTOK*EE];
__device__ __half g_H1h[(long)NTOK*FF];
__device__ float  g_Z[(long)NTOK*EE];

// ---------------- PTX helpers ----------------
__device__ __forceinline__ uint32_t smem_u32(const void* p) {
    uint32_t a;
    asm("{ .reg .u64 t; cvta.to.shared.u64 t, %1; cvt.u32.u64 %0, t; }" : "=r"(a) : "l"(p));
    return a;
}
__device__ __forceinline__ void cp16(uint32_t dst, const void* src) {
    asm volatile("cp.async.cg.shared.global [%0], [%1], 16;" :: "r"(dst), "l"(src));
}

// ---------------- HMMA f16 GEMM: C[M,N] = A[M,K] * B[N,K]^T ----------------
// A, B half, K-major (K contiguous). BM=128 fixed, BK=64. K % 64 == 0.
// 256 threads = 8 warps (4 m x 2 n). Warp tile: 32 x (BN/2).
template<int BN, bool OUT_HALF>
__global__ __launch_bounds__(256)
void hgemm_kernel(const __half* __restrict__ A, const __half* __restrict__ B,
                  void* __restrict__ Cv, int K, int lda, int ldb, int ldc,
                  long sA1, long sA2, long sB1, long sB2, long sC1, long sC2, int Z2,
                  const float* __restrict__ bias, const float* __restrict__ residual,
                  int ldr, int do_relu, int do_exp)
{
    constexpr int BM = 128;
    constexpr int STG_A = BM * 128;       // bytes per A stage (128B = 64 halfs per row)
    constexpr int STG_B = BN * 128;
    constexpr int STG   = STG_A + STG_B;
    constexpr int WN = BN / 2;            // warp n extent
    constexpr int NT = WN / 8;            // n-tiles (m16n8k16) per warp

    extern __shared__ char smem_raw[];
    const uint32_t sb0   = smem_u32(smem_raw);
    const uint32_t sbase = (sb0 + 127u) & ~127u;

    const int tid  = threadIdx.x;
    const int lane = tid & 31;
    const int wid  = tid >> 5;
    const int wm   = (wid & 3) << 5;      // warp m offset (0,32,64,96)
    const int wn   = (wid >> 2) * WN;     // warp n offset

    const int z  = blockIdx.z;
    const int z1 = z / Z2, z2 = z - z1 * Z2;
    A += z1 * sA1 + z2 * sA2;
    B += z1 * sB1 + z2 * sB2;
    const long coff = z1 * sC1 + z2 * sC2;
    const int m0 = blockIdx.y * BM;
    const int n0 = blockIdx.x * BN;

    float acc[2][NT][4];
    #pragma unroll
    for (int i = 0; i < 2; i++)
        #pragma unroll
        for (int j = 0; j < NT; j++)
            #pragma unroll
            for (int k = 0; k < 4; k++) acc[i][j][k] = 0.0f;

    const int nK = K >> 6;

    auto load_stage = [&](int stg, int kt) {
        uint32_t sA = sbase + stg * STG;
        const char* Ab = (const char*)(A + (long)m0 * lda + kt * 64);
        #pragma unroll
        for (int idx = tid; idx < BM * 8; idx += 256) {
            int r = idx >> 3, c = (idx & 7) << 4;
            uint32_t off = (uint32_t)(r * 128 + c); off ^= (off >> 3) & 0x70;
            cp16(sA + off, Ab + (long)r * lda * 2 + c);
        }
        uint32_t sB = sbase + stg * STG + STG_A;
        const char* Bb = (const char*)(B + (long)n0 * ldb + kt * 64);
        #pragma unroll
        for (int idx = tid; idx < BN * 8; idx += 256) {
            int r = idx >> 3, c = (idx & 7) << 4;
            uint32_t off = (uint32_t)(r * 128 + c); off ^= (off >> 3) & 0x70;
            cp16(sB + off, Bb + (long)r * ldb * 2 + c);
        }
        asm volatile("cp.async.commit_group;" ::: "memory");
    };

    load_stage(0, 0);

    for (int i = 0; i < nK; i++) {
        const int cur = i & 1;
        if (i + 1 < nK) {
            load_stage(1 - cur, i + 1);
            asm volatile("cp.async.wait_group 1;" ::: "memory");
        } else {
            asm volatile("cp.async.wait_group 0;" ::: "memory");
        }
        __syncthreads();

        const uint32_t sA = sbase + cur * STG;
        const uint32_t sB = sA + STG_A;
        #pragma unroll
        for (int ks = 0; ks < 4; ks++) {
            uint32_t a[2][4];
            #pragma unroll
            for (int mt = 0; mt < 2; mt++) {
                int m = wm + (mt << 4) + (lane & 15);
                uint32_t off = (uint32_t)((m << 7) + (ks << 5) + ((lane >> 4) << 4));
                off ^= (off >> 3) & 0x70;
                asm volatile("ldmatrix.sync.aligned.m8n8.x4.shared.b16 {%0,%1,%2,%3}, [%4];"
                    : "=r"(a[mt][0]), "=r"(a[mt][1]), "=r"(a[mt][2]), "=r"(a[mt][3])
                    : "r"(sA + off));
            }
            uint32_t b[NT][2];
            #pragma unroll
            for (int p = 0; p < NT / 2; p++) {
                int quad = lane >> 3;
                int n = wn + (p << 4) + ((quad & 2) << 2) + (lane & 7);
                uint32_t off = (uint32_t)((n << 7) + (ks << 5) + ((quad & 1) << 4));
                off ^= (off >> 3) & 0x70;
                asm volatile("ldmatrix.sync.aligned.m8n8.x4.shared.b16 {%0,%1,%2,%3}, [%4];"
                    : "=r"(b[2*p][0]), "=r"(b[2*p][1]), "=r"(b[2*p+1][0]), "=r"(b[2*p+1][1])
                    : "r"(sB + off));
            }
            #pragma unroll
            for (int mt = 0; mt < 2; mt++)
                #pragma unroll
                for (int nt = 0; nt < NT; nt++)
                    asm volatile("mma.sync.aligned.m16n8k16.row.col.f32.f16.f16.f32 "
                        "{%0,%1,%2,%3}, {%4,%5,%6,%7}, {%8,%9}, {%0,%1,%2,%3};"
                        : "+f"(acc[mt][nt][0]), "+f"(acc[mt][nt][1]),
                          "+f"(acc[mt][nt][2]), "+f"(acc[mt][nt][3])
                        : "r"(a[mt][0]), "r"(a[mt][1]), "r"(a[mt][2]), "r"(a[mt][3]),
                          "r"(b[nt][0]), "r"(b[nt][1]));
        }
        __syncthreads();
    }

    // -------- epilogue: register fragments -> global (fused bias/residual/relu/exp) --
    const int mrow = lane >> 2;
    const int ncol = (lane & 3) << 1;
    #pragma unroll
    for (int mt = 0; mt < 2; mt++) {
        #pragma unroll
        for (int nt = 0; nt < NT; nt++) {
            long gm = m0 + wm + (mt << 4) + mrow;
            int  gn = n0 + wn + (nt << 3) + ncol;
            float v0 = acc[mt][nt][0], v1 = acc[mt][nt][1];
            float v2 = acc[mt][nt][2], v3 = acc[mt][nt][3];
            if (bias) {
                float b0 = bias[gn], b1 = bias[gn + 1];
                v0 += b0; v1 += b1; v2 += b0; v3 += b1;
            }
            if (residual) {
                v0 += residual[gm * ldr + gn];       v1 += residual[gm * ldr + gn + 1];
                v2 += residual[(gm + 8) * ldr + gn]; v3 += residual[(gm + 8) * ldr + gn + 1];
            }
            if (do_relu) {
                v0 = fmaxf(v0, 0.0f); v1 = fmaxf(v1, 0.0f);
                v2 = fmaxf(v2, 0.0f); v3 = fmaxf(v3, 0.0f);
            }
            if (do_exp) {
                v0 = fminf(__expf(v0 - EXP_SHIFT), 60000.0f);
                v1 = fminf(__expf(v1 - EXP_SHIFT), 60000.0f);
                v2 = fminf(__expf(v2 - EXP_SHIFT), 60000.0f);
                v3 = fminf(__expf(v3 - EXP_SHIFT), 60000.0f);
            }
            if (OUT_HALF) {
                *(__half2*)((__half*)Cv + coff + gm * ldc + gn)       = __floats2half2_rn(v0, v1);
                *(__half2*)((__half*)Cv + coff + (gm + 8) * ldc + gn) = __floats2half2_rn(v2, v3);
            } else {
                float* p0 = (float*)Cv + coff + gm * ldc + gn;
                p0[0] = v0; p0[1] = v1;
                float* p1 = (float*)Cv + coff + (gm + 8) * ldc + gn;
                p1[0] = v2; p1[1] = v3;
            }
        }
    }
}

// ---------------- conversion / packing kernels ----------------
__global__ __launch_bounds__(256) void f2h_kernel(const float* __restrict__ s,
                                                  __half* __restrict__ d, long n) {
    long i = (long)blockIdx.x * 256 + threadIdx.x;
    if (i < n) d[i] = __float2half(s[i]);
}
__global__ __launch_bounds__(256) void pack_qk_kernel(const float* __restrict__ WQ,
                                                      const float* __restrict__ WK,
                                                      __half* __restrict__ dst) {
    long i = (long)blockIdx.x * 256 + threadIdx.x;   // over 2048*1024
    int n = (int)(i >> 10), e = (int)(i & 1023);
    const float* W = (n < 1024) ? WQ : WK;
    int hd = n & 1023; int h = hd >> 6, d = hd & 63;
    dst[i] = __float2half(W[((long)h * 1024 + e) * 64 + d]);
}
__global__ __launch_bounds__(256) void pack_vt_kernel(const float* __restrict__ WV,
                                                      __half* __restrict__ dst) {
    long i = (long)blockIdx.x * 256 + threadIdx.x;   // over 1024*1024
    int n = (int)(i >> 10), e = (int)(i & 1023);
    int h = n >> 6, d = n & 63;
    dst[i] = __float2half(WV[((long)h * 1024 + e) * 64 + d]);
}
__global__ __launch_bounds__(256) void transpose_h_kernel(const float* __restrict__ src,
                                                          __half* __restrict__ dst,
                                                          int R, int C) {
    long i = (long)blockIdx.x * 256 + threadIdx.x;   // i = c*R + r
    if (i >= (long)R * C) return;
    int c = (int)(i / R), r = (int)(i % R);
    dst[i] = __float2half(src[(long)r * C + c]);
}

// ---------------- column sums of att -> inv = 0.125/sum (deterministic) ------
// att [z][s][t] half; sum over s per (z,t). Each thread handles 2 adjacent t.
__global__ __launch_bounds__(256) void colsum_kernel(const __half* __restrict__ att,
                                                     float* __restrict__ inv) {
    long z = blockIdx.y;
    int  t2 = (blockIdx.x * 256 + threadIdx.x) * 2;
    const __half* p = att + z * (long)SS * SS + t2;
    float s0 = 0.0f, s1 = 0.0f;
    #pragma unroll 4
    for (int s = 0; s < SS; s++) {
        float2 f = __half22float2(*(const __half2*)(p + (long)s * SS));
        s0 += f.x; s1 += f.y;
    }
    inv[z * (long)SS + t2]     = 0.125f / s0;
    inv[z * (long)SS + t2 + 1] = 0.125f / s1;
}

// ---------------- scale Vth rows by inv (folds softmax normalization) --------
// Vth [b][hd][t] *= inv[(b*HH + (hd>>6))][t]
__global__ __launch_bounds__(256) void vscale_kernel(__half* __restrict__ v,
                                                     const float* __restrict__ inv) {
    long i2 = (long)blockIdx.x * 256 + threadIdx.x;     // over elements/2
    long i  = i2 * 2;
    if (i >= (long)BB * 1024 * SS) return;
    int t  = (int)(i & (SS - 1));
    int hd = (int)((i >> 11) & 1023);
    int b  = (int)(i >> 21);
    const float* ip = inv + ((long)(b * HH + (hd >> 6))) * SS + t;
    __half2* p = (__half2*)(v + i);
    float2 f = __half22float2(*p);
    f.x *= ip[0]; f.y *= ip[1];
    *p = __floats2half2_rn(f.x, f.y);
}

// ---------------- layernorm (E=1024), optional half copy ----------------
__global__ __launch_bounds__(256)
void layernorm_kernel(const float* __restrict__ x, const float* __restrict__ gamma,
                      const float* __restrict__ beta, float* __restrict__ outf,
                      __half* __restrict__ outh) {
    long row = blockIdx.x;
    const float* p = x + row * (long)EE;
    const int tid = threadIdx.x, lane = tid & 31, warp = tid >> 5;

    float v[4]; float s = 0.0f;
    #pragma unroll
    for (int i = 0; i < 4; i++) { v[i] = p[tid + i * 256]; s += v[i]; }
    __shared__ float red1[8], red2[8];
    #pragma unroll
    for (int o = 16; o > 0; o >>= 1) s += __shfl_xor_sync(0xffffffffu, s, o);
    if (lane == 0) red1[warp] = s;
    __syncthreads();
    float tot = red1[0];
    #pragma unroll
    for (int i = 1; i < 8; i++) tot += red1[i];
    float mu = tot * (1.0f / EE);

    float q = 0.0f;
    #pragma unroll
    for (int i = 0; i < 4; i++) { float d = v[i] - mu; q += d * d; }
    #pragma unroll
    for (int o = 16; o > 0; o >>= 1) q += __shfl_xor_sync(0xffffffffu, q, o);
    if (lane == 0) red2[warp] = q;
    __syncthreads();
    float qt = red2[0];
    #pragma unroll
    for (int i = 1; i < 8; i++) qt += red2[i];
    float rstd = rsqrtf(qt * (1.0f / EE) + LN_EPS);

    #pragma unroll
    for (int i = 0; i < 4; i++) {
        int col = tid + i * 256;
        float y = (v[i] - mu) * rstd * gamma[col] + beta[col];
        outf[row * (long)EE + col] = y;
        if (outh) outh[row * (long)EE + col] = __float2half(y);
    }
}

// ---------------- launcher ----------------
extern "C" void kernel_launch(void* const* d_in, const int* in_sizes, int n_in,
                              void* d_out, int out_size)
{
    const float* X     = (const float*)d_in[0];
    const float* WQ    = (const float*)d_in[1];
    const float* WK    = (const float*)d_in[2];
    const float* WV    = (const float*)d_in[3];
    const float* WO    = (const float*)d_in[4];
    const float* gamma = (const float*)d_in[5];
    const float* beta  = (const float*)d_in[6];
    const float* W1    = (const float*)d_in[7];
    const float* b1    = (const float*)d_in[8];
    const float* W2    = (const float*)d_in[9];
    const float* b2    = (const float*)d_in[10];
    float* out = (float*)d_out;

    __half *Xh, *Wqk, *Wvt, *Wot, *W1t, *W2t, *QKh, *Vth, *ATT, *AVh, *VAh, *H1h;
    float *INV, *Y, *VAf, *Z;
    cudaGetSymbolAddress((void**)&Xh,  g_Xh);
    cudaGetSymbolAddress((void**)&Wqk, g_Wqk);
    cudaGetSymbolAddress((void**)&Wvt, g_Wvt);
    cudaGetSymbolAddress((void**)&Wot, g_Wot);
    cudaGetSymbolAddress((void**)&W1t, g_W1t);
    cudaGetSymbolAddress((void**)&W2t, g_W2t);
    cudaGetSymbolAddress((void**)&QKh, g_QKh);
    cudaGetSymbolAddress((void**)&Vth, g_Vth);
    cudaGetSymbolAddress((void**)&ATT, g_att);
    cudaGetSymbolAddress((void**)&INV, g_inv);
    cudaGetSymbolAddress((void**)&AVh, g_AVh);
    cudaGetSymbolAddress((void**)&Y,   g_Y);
    cudaGetSymbolAddress((void**)&VAf, g_VAf);
    cudaGetSymbolAddress((void**)&VAh, g_VAh);
    cudaGetSymbolAddress((void**)&H1h, g_H1h);
    cudaGetSymbolAddress((void**)&Z,   g_Z);

    const int SM128 = 2 * (128 * 128 + 128 * 128) + 256;   // 65792 bytes
    const int SM64  = 2 * (128 * 128 +  64 * 128) + 256;   // 49408 bytes
    cudaFuncSetAttribute(hgemm_kernel<128, true>,  cudaFuncAttributeMaxDynamicSharedMemorySize, SM128);
    cudaFuncSetAttribute(hgemm_kernel<128, false>, cudaFuncAttributeMaxDynamicSharedMemorySize, SM128);
    cudaFuncSetAttribute(hgemm_kernel<64,  true>,  cudaFuncAttributeMaxDynamicSharedMemorySize, SM64);

    const long SSl = SS, SSS = SSl * SSl;
    dim3 blk(256);

    // 0) conversions / packing
    f2h_kernel<<<(NTOK * (long)EE) / 256, blk>>>(X, Xh, (long)NTOK * EE);
    pack_qk_kernel<<<(2048L * EE) / 256, blk>>>(WQ, WK, Wqk);
    pack_vt_kernel<<<(1024L * EE) / 256, blk>>>(WV, Wvt);
    transpose_h_kernel<<<(1024L * 1024) / 256, blk>>>(WO, Wot, 1024, 1024);
    transpose_h_kernel<<<((long)EE * FF) / 256, blk>>>(W1, W1t, EE, FF);   // dst [F][E]
    transpose_h_kernel<<<((long)FF * EE) / 256, blk>>>(W2, W2t, FF, EE);   // dst [E][F]

    // 1) QK projection: [8192,1024] x [2048,1024]^T -> QKh [8192,2048] half
    hgemm_kernel<128, true><<<dim3(2048 / 128, NTOK / 128, 1), blk, SM128>>>(
        Xh, Wqk, QKh, EE, EE, EE, 2048,
        0, 0, 0, 0, 0, 0, 1, nullptr, nullptr, 0, 0, 0);

    // 2) Vt: per b: [1024,1024](Wvt) x [2048,1024](Xh_b)^T -> Vth[b][1024,2048] half
    hgemm_kernel<128, true><<<dim3(SS / 128, 1024 / 128, BB), blk, SM128>>>(
        Wvt, Xh, Vth, EE, EE, EE, SS,
        0, 0, (long)SS * EE, 0, 1024L * SS, 0, 1, nullptr, nullptr, 0, 0, 0);

    // 3) scores + exp: per (b,h): Q[2048,64] x K[2048,64]^T -> att = exp(. - 12) half
    hgemm_kernel<128, true><<<dim3(SS / 128, SS / 128, BB * HH), blk, SM128>>>(
        QKh, QKh + 1024, ATT, DD, 2048, 2048, SS,
        SSl * 2048, 64, SSl * 2048, 64, (long)HH * SSS, SSS, HH,
        nullptr, nullptr, 0, 0, 1);

    // 4) column sums (query axis) -> inv = 0.125/sum; fold into V
    colsum_kernel<<<dim3(SS / 512, BB * HH), blk>>>(ATT, INV);
    vscale_kernel<<<(int)(((long)BB * 1024 * SS / 2 + 255) / 256), blk>>>(Vth, INV);

    // 5) AV: per (b,h): att[2048,2048] x Vt'[64,2048]^T -> AVh[b*S+s][h*64+d]
    hgemm_kernel<64, true><<<dim3(1, SS / 128, BB * HH), blk, SM64>>>(
        ATT, Vth, AVh, SS, SS, SS, EE,
        (long)HH * SSS, SSS, 1024L * SS, 64L * SS, SSl * EE, 64, HH,
        nullptr, nullptr, 0, 0, 0);

    // 6) WO: [8192,1024] x [1024,1024]^T + X -> Y fp32; LN -> VAf/VAh
    hgemm_kernel<128, false><<<dim3(EE / 128, NTOK / 128, 1), blk, SM128>>>(
        AVh, Wot, Y, 1024, 1024, 1024, EE,
        0, 0, 0, 0, 0, 0, 1, nullptr, X, EE, 0, 0);
    layernorm_kernel<<<NTOK, blk>>>(Y, gamma, beta, VAf, VAh);

    // 7) FFN1: [8192,1024] x [4096,1024]^T + b1, relu -> H1h half
    hgemm_kernel<128, true><<<dim3(FF / 128, NTOK / 128, 1), blk, SM128>>>(
        VAh, W1t, H1h, EE, EE, EE, FF,
        0, 0, 0, 0, 0, 0, 1, b1, nullptr, 0, 1, 0);

    // 8) FFN2: [8192,4096] x [1024,4096]^T + b2 + VAf -> Z fp32; LN -> out
    hgemm_kernel<128, false><<<dim3(EE / 128, NTOK / 128, 1), blk, SM128>>>(
        H1h, W2t, Z, FF, FF, FF, EE,
        0, 0, 0, 0, 0, 0, 1, b2, VAf, EE, 0, 0);
    layernorm_kernel<<<NTOK, blk>>>(Z, gamma, beta, out, nullptr);
}

// round 6
// speedup vs baseline: 5.6795x; 1.1669x over previous
#include <cuda_runtime.h>
#include <cuda_fp16.h>
#include <cstdint>

#define BB 4
#define SS 2048
#define EE 1024
#define HH 16
#define DD 64
#define FF 4096
#define LN_EPS 1e-5f
#define NTOK (BB*SS)
#define EXP_SHIFT 12.0f

// ---------------- scratch (device globals) ----------------
__device__ __half g_Xh[(long)NTOK*EE];
__device__ __half g_Wqk[2048L*EE];          // rows: [Q(h*64+d) | K(h*64+d)], cols e
__device__ __half g_Wvt[1024L*EE];          // rows h*64+d, cols e
__device__ __half g_Wot[1024L*1024];        // rows e_out, cols hd
__device__ __half g_W1t[(long)FF*EE];       // rows f, cols e
__device__ __half g_W2t[(long)EE*FF];       // rows e, cols f
__device__ __half g_QKh[(long)NTOK*2048];   // [b*S+s][ Q: h*64+d , K: 1024+h*64+d ]
__device__ __half g_Vth[(long)BB*1024*SS];  // [b][h*64+d][t]
__device__ __half g_att[268435456L];        // [b,h][s][t]  unnormalized exp (0.5 GB)
__device__ float  g_inv[(long)BB*HH*SS];    // 0.125 / colsum per (z,t)
__device__ __half g_AVh[(long)NTOK*EE];     // [b*S+s][h*64+d]
__device__ float  g_Y[(long)NTOK*EE];
__device__ float  g_VAf[(long)NTOK*EE];
__device__ __half g_VAh[(long)NTOK*EE];
__device__ __half g_H1h[(long)NTOK*FF];
__device__ float  g_Z[(long)NTOK*EE];

// ---------------- PTX helpers ----------------
__device__ __forceinline__ uint32_t smem_u32(const void* p) {
    uint32_t a;
    asm("{ .reg .u64 t; cvta.to.shared.u64 t, %1; cvt.u32.u64 %0, t; }" : "=r"(a) : "l"(p));
    return a;
}
__device__ __forceinline__ void cp16(uint32_t dst, const void* src) {
    asm volatile("cp.async.cg.shared.global [%0], [%1], 16;" :: "r"(dst), "l"(src));
}

// ---------------- HMMA f16 GEMM: C[M,N] = A[M,K] * B[N,K]^T ----------------
// A, B half, K-major. BM=128, BK=64, 128 threads = 4 warps (2m x 2n), warp 64xWN.
// 3-stage cp.async pipeline, one __syncthreads per k-iter.
template<int BN, bool OUT_HALF>
__global__ __launch_bounds__(128)
void hgemm_kernel(const __half* __restrict__ A, const __half* __restrict__ B,
                  void* __restrict__ Cv, int K, int lda, int ldb, int ldc,
                  long sA1, long sA2, long sB1, long sB2, long sC1, long sC2, int Z2,
                  const float* __restrict__ bias, const float* __restrict__ residual,
                  int ldr, int do_relu, int do_exp)
{
    constexpr int BM = 128;
    constexpr int STG_A = BM * 128;       // bytes per A stage (128B = 64 halfs per row)
    constexpr int STG_B = BN * 128;
    constexpr int STG   = STG_A + STG_B;
    constexpr int WN = BN / 2;            // warp n extent
    constexpr int MT = 4;                 // m16 tiles per warp (64 rows)
    constexpr int NT = WN / 8;            // n8 tiles per warp

    extern __shared__ char smem_raw[];
    const uint32_t sb0   = smem_u32(smem_raw);
    const uint32_t sbase = (sb0 + 127u) & ~127u;

    const int tid  = threadIdx.x;
    const int lane = tid & 31;
    const int wid  = tid >> 5;
    const int wm   = (wid & 1) << 6;      // warp m offset (0, 64)
    const int wn   = (wid >> 1) * WN;     // warp n offset

    const int z  = blockIdx.z;
    const int z1 = z / Z2, z2 = z - z1 * Z2;
    A += z1 * sA1 + z2 * sA2;
    B += z1 * sB1 + z2 * sB2;
    const long coff = z1 * sC1 + z2 * sC2;
    const int m0 = blockIdx.y * BM;
    const int n0 = blockIdx.x * BN;

    float acc[MT][NT][4];
    #pragma unroll
    for (int i = 0; i < MT; i++)
        #pragma unroll
        for (int j = 0; j < NT; j++)
            #pragma unroll
            for (int k = 0; k < 4; k++) acc[i][j][k] = 0.0f;

    const int nK = K >> 6;

    auto load_stage = [&](int stg, int kt) {
        uint32_t sA = sbase + stg * STG;
        const char* Ab = (const char*)(A + (long)m0 * lda + kt * 64);
        #pragma unroll
        for (int idx = tid; idx < BM * 8; idx += 128) {
            int r = idx >> 3, c = (idx & 7) << 4;
            uint32_t off = (uint32_t)(r * 128 + c); off ^= (off >> 3) & 0x70;
            cp16(sA + off, Ab + (long)r * lda * 2 + c);
        }
        uint32_t sB = sbase + stg * STG + STG_A;
        const char* Bb = (const char*)(B + (long)n0 * ldb + kt * 64);
        #pragma unroll
        for (int idx = tid; idx < BN * 8; idx += 128) {
            int r = idx >> 3, c = (idx & 7) << 4;
            uint32_t off = (uint32_t)(r * 128 + c); off ^= (off >> 3) & 0x70;
            cp16(sB + off, Bb + (long)r * ldb * 2 + c);
        }
        asm volatile("cp.async.commit_group;" ::: "memory");
    };

    load_stage(0, 0);
    if (nK > 1) load_stage(1, 1);

    for (int i = 0; i < nK; i++) {
        if (i + 1 < nK) asm volatile("cp.async.wait_group 1;" ::: "memory");
        else            asm volatile("cp.async.wait_group 0;" ::: "memory");
        __syncthreads();
        if (i + 2 < nK) {
            int st = (i + 2) % 3;
            load_stage(st, i + 2);
        }

        const uint32_t sA = sbase + (i % 3) * STG;
        const uint32_t sB = sA + STG_A;
        #pragma unroll
        for (int ks = 0; ks < 4; ks++) {
            uint32_t a[MT][4];
            #pragma unroll
            for (int mt = 0; mt < MT; mt++) {
                int m = wm + (mt << 4) + (lane & 15);
                uint32_t off = (uint32_t)((m << 7) + (ks << 5) + ((lane >> 4) << 4));
                off ^= (off >> 3) & 0x70;
                asm volatile("ldmatrix.sync.aligned.m8n8.x4.shared.b16 {%0,%1,%2,%3}, [%4];"
                    : "=r"(a[mt][0]), "=r"(a[mt][1]), "=r"(a[mt][2]), "=r"(a[mt][3])
                    : "r"(sA + off));
            }
            uint32_t b[NT][2];
            #pragma unroll
            for (int p = 0; p < NT / 2; p++) {
                int quad = lane >> 3;
                int n = wn + (p << 4) + ((quad & 2) << 2) + (lane & 7);
                uint32_t off = (uint32_t)((n << 7) + (ks << 5) + ((quad & 1) << 4));
                off ^= (off >> 3) & 0x70;
                asm volatile("ldmatrix.sync.aligned.m8n8.x4.shared.b16 {%0,%1,%2,%3}, [%4];"
                    : "=r"(b[2*p][0]), "=r"(b[2*p][1]), "=r"(b[2*p+1][0]), "=r"(b[2*p+1][1])
                    : "r"(sB + off));
            }
            #pragma unroll
            for (int mt = 0; mt < MT; mt++)
                #pragma unroll
                for (int nt = 0; nt < NT; nt++)
                    asm volatile("mma.sync.aligned.m16n8k16.row.col.f32.f16.f16.f32 "
                        "{%0,%1,%2,%3}, {%4,%5,%6,%7}, {%8,%9}, {%0,%1,%2,%3};"
                        : "+f"(acc[mt][nt][0]), "+f"(acc[mt][nt][1]),
                          "+f"(acc[mt][nt][2]), "+f"(acc[mt][nt][3])
                        : "r"(a[mt][0]), "r"(a[mt][1]), "r"(a[mt][2]), "r"(a[mt][3]),
                          "r"(b[nt][0]), "r"(b[nt][1]));
        }
    }

    // -------- epilogue: register fragments -> global (fused bias/residual/relu/exp) --
    const int mrow = lane >> 2;
    const int ncol = (lane & 3) << 1;
    #pragma unroll
    for (int mt = 0; mt < MT; mt++) {
        #pragma unroll
        for (int nt = 0; nt < NT; nt++) {
            long gm = m0 + wm + (mt << 4) + mrow;
            int  gn = n0 + wn + (nt << 3) + ncol;
            float v0 = acc[mt][nt][0], v1 = acc[mt][nt][1];
            float v2 = acc[mt][nt][2], v3 = acc[mt][nt][3];
            if (bias) {
                float b0 = bias[gn], b1 = bias[gn + 1];
                v0 += b0; v1 += b1; v2 += b0; v3 += b1;
            }
            if (residual) {
                const float2 r0 = *(const float2*)(residual + gm * ldr + gn);
                const float2 r1 = *(const float2*)(residual + (gm + 8) * ldr + gn);
                v0 += r0.x; v1 += r0.y; v2 += r1.x; v3 += r1.y;
            }
            if (do_relu) {
                v0 = fmaxf(v0, 0.0f); v1 = fmaxf(v1, 0.0f);
                v2 = fmaxf(v2, 0.0f); v3 = fmaxf(v3, 0.0f);
            }
            if (do_exp) {
                v0 = fminf(__expf(v0 - EXP_SHIFT), 60000.0f);
                v1 = fminf(__expf(v1 - EXP_SHIFT), 60000.0f);
                v2 = fminf(__expf(v2 - EXP_SHIFT), 60000.0f);
                v3 = fminf(__expf(v3 - EXP_SHIFT), 60000.0f);
            }
            if (OUT_HALF) {
                *(__half2*)((__half*)Cv + coff + gm * ldc + gn)       = __floats2half2_rn(v0, v1);
                *(__half2*)((__half*)Cv + coff + (gm + 8) * ldc + gn) = __floats2half2_rn(v2, v3);
            } else {
                *(float2*)((float*)Cv + coff + gm * ldc + gn)       = make_float2(v0, v1);
                *(float2*)((float*)Cv + coff + (gm + 8) * ldc + gn) = make_float2(v2, v3);
            }
        }
    }
}

// ---------------- conversion / packing kernels ----------------
__global__ __launch_bounds__(256) void f2h_kernel(const float* __restrict__ s,
                                                  __half* __restrict__ d, long n) {
    long i = (long)blockIdx.x * 256 + threadIdx.x;
    if (i < n) d[i] = __float2half(s[i]);
}
__global__ __launch_bounds__(256) void pack_qk_kernel(const float* __restrict__ WQ,
                                                      const float* __restrict__ WK,
                                                      __half* __restrict__ dst) {
    long i = (long)blockIdx.x * 256 + threadIdx.x;   // over 2048*1024
    int n = (int)(i >> 10), e = (int)(i & 1023);
    const float* W = (n < 1024) ? WQ : WK;
    int hd = n & 1023; int h = hd >> 6, d = hd & 63;
    dst[i] = __float2half(W[((long)h * 1024 + e) * 64 + d]);
}
__global__ __launch_bounds__(256) void pack_vt_kernel(const float* __restrict__ WV,
                                                      __half* __restrict__ dst) {
    long i = (long)blockIdx.x * 256 + threadIdx.x;   // over 1024*1024
    int n = (int)(i >> 10), e = (int)(i & 1023);
    int h = n >> 6, d = n & 63;
    dst[i] = __float2half(WV[((long)h * 1024 + e) * 64 + d]);
}
__global__ __launch_bounds__(256) void transpose_h_kernel(const float* __restrict__ src,
                                                          __half* __restrict__ dst,
                                                          int R, int C) {
    long i = (long)blockIdx.x * 256 + threadIdx.x;   // i = c*R + r
    if (i >= (long)R * C) return;
    int c = (int)(i / R), r = (int)(i % R);
    dst[i] = __float2half(src[(long)r * C + c]);
}

// ---------------- column sums of att -> inv = 0.125/sum (deterministic) ------
__global__ __launch_bounds__(256) void colsum_kernel(const __half* __restrict__ att,
                                                     float* __restrict__ inv) {
    long z = blockIdx.y;
    int  t2 = (blockIdx.x * 256 + threadIdx.x) * 2;
    const __half* p = att + z * (long)SS * SS + t2;
    float s0 = 0.0f, s1 = 0.0f;
    #pragma unroll 4
    for (int s = 0; s < SS; s++) {
        float2 f = __half22float2(*(const __half2*)(p + (long)s * SS));
        s0 += f.x; s1 += f.y;
    }
    inv[z * (long)SS + t2]     = 0.125f / s0;
    inv[z * (long)SS + t2 + 1] = 0.125f / s1;
}

// ---------------- scale Vth rows by inv (folds softmax normalization) --------
__global__ __launch_bounds__(256) void vscale_kernel(__half* __restrict__ v,
                                                     const float* __restrict__ inv) {
    long i2 = (long)blockIdx.x * 256 + threadIdx.x;     // over elements/2
    long i  = i2 * 2;
    if (i >= (long)BB * 1024 * SS) return;
    int t  = (int)(i & (SS - 1));
    int hd = (int)((i >> 11) & 1023);
    int b  = (int)(i >> 21);
    const float* ip = inv + ((long)(b * HH + (hd >> 6))) * SS + t;
    __half2* p = (__half2*)(v + i);
    float2 f = __half22float2(*p);
    f.x *= ip[0]; f.y *= ip[1];
    *p = __floats2half2_rn(f.x, f.y);
}

// ---------------- layernorm (E=1024), optional half copy ----------------
__global__ __launch_bounds__(256)
void layernorm_kernel(const float* __restrict__ x, const float* __restrict__ gamma,
                      const float* __restrict__ beta, float* __restrict__ outf,
                      __half* __restrict__ outh) {
    long row = blockIdx.x;
    const float* p = x + row * (long)EE;
    const int tid = threadIdx.x, lane = tid & 31, warp = tid >> 5;

    float v[4]; float s = 0.0f;
    #pragma unroll
    for (int i = 0; i < 4; i++) { v[i] = p[tid + i * 256]; s += v[i]; }
    __shared__ float red1[8], red2[8];
    #pragma unroll
    for (int o = 16; o > 0; o >>= 1) s += __shfl_xor_sync(0xffffffffu, s, o);
    if (lane == 0) red1[warp] = s;
    __syncthreads();
    float tot = red1[0];
    #pragma unroll
    for (int i = 1; i < 8; i++) tot += red1[i];
    float mu = tot * (1.0f / EE);

    float q = 0.0f;
    #pragma unroll
    for (int i = 0; i < 4; i++) { float d = v[i] - mu; q += d * d; }
    #pragma unroll
    for (int o = 16; o > 0; o >>= 1) q += __shfl_xor_sync(0xffffffffu, q, o);
    if (lane == 0) red2[warp] = q;
    __syncthreads();
    float qt = red2[0];
    #pragma unroll
    for (int i = 1; i < 8; i++) qt += red2[i];
    float rstd = rsqrtf(qt * (1.0f / EE) + LN_EPS);

    #pragma unroll
    for (int i = 0; i < 4; i++) {
        int col = tid + i * 256;
        float y = (v[i] - mu) * rstd * gamma[col] + beta[col];
        outf[row * (long)EE + col] = y;
        if (outh) outh[row * (long)EE + col] = __float2half(y);
    }
}

// ---------------- launcher ----------------
extern "C" void kernel_launch(void* const* d_in, const int* in_sizes, int n_in,
                              void* d_out, int out_size)
{
    const float* X     = (const float*)d_in[0];
    const float* WQ    = (const float*)d_in[1];
    const float* WK    = (const float*)d_in[2];
    const float* WV    = (const float*)d_in[3];
    const float* WO    = (const float*)d_in[4];
    const float* gamma = (const float*)d_in[5];
    const float* beta  = (const float*)d_in[6];
    const float* W1    = (const float*)d_in[7];
    const float* b1    = (const float*)d_in[8];
    const float* W2    = (const float*)d_in[9];
    const float* b2    = (const float*)d_in[10];
    float* out = (float*)d_out;

    __half *Xh, *Wqk, *Wvt, *Wot, *W1t, *W2t, *QKh, *Vth, *ATT, *AVh, *VAh, *H1h;
    float *INV, *Y, *VAf, *Z;
    cudaGetSymbolAddress((void**)&Xh,  g_Xh);
    cudaGetSymbolAddress((void**)&Wqk, g_Wqk);
    cudaGetSymbolAddress((void**)&Wvt, g_Wvt);
    cudaGetSymbolAddress((void**)&Wot, g_Wot);
    cudaGetSymbolAddress((void**)&W1t, g_W1t);
    cudaGetSymbolAddress((void**)&W2t, g_W2t);
    cudaGetSymbolAddress((void**)&QKh, g_QKh);
    cudaGetSymbolAddress((void**)&Vth, g_Vth);
    cudaGetSymbolAddress((void**)&ATT, g_att);
    cudaGetSymbolAddress((void**)&INV, g_inv);
    cudaGetSymbolAddress((void**)&AVh, g_AVh);
    cudaGetSymbolAddress((void**)&Y,   g_Y);
    cudaGetSymbolAddress((void**)&VAf, g_VAf);
    cudaGetSymbolAddress((void**)&VAh, g_VAh);
    cudaGetSymbolAddress((void**)&H1h, g_H1h);
    cudaGetSymbolAddress((void**)&Z,   g_Z);

    const int SM128 = 3 * (128 * 128 + 128 * 128) + 256;   // 98560 bytes
    const int SM64  = 3 * (128 * 128 +  64 * 128) + 256;   // 73984 bytes
    cudaFuncSetAttribute(hgemm_kernel<128, true>,  cudaFuncAttributeMaxDynamicSharedMemorySize, SM128);
    cudaFuncSetAttribute(hgemm_kernel<128, false>, cudaFuncAttributeMaxDynamicSharedMemorySize, SM128);
    cudaFuncSetAttribute(hgemm_kernel<64,  true>,  cudaFuncAttributeMaxDynamicSharedMemorySize, SM64);

    const long SSl = SS, SSS = SSl * SSl;
    dim3 blk(256);
    dim3 gblk(128);

    // 0) conversions / packing
    f2h_kernel<<<(NTOK * (long)EE) / 256, blk>>>(X, Xh, (long)NTOK * EE);
    pack_qk_kernel<<<(2048L * EE) / 256, blk>>>(WQ, WK, Wqk);
    pack_vt_kernel<<<(1024L * EE) / 256, blk>>>(WV, Wvt);
    transpose_h_kernel<<<(1024L * 1024) / 256, blk>>>(WO, Wot, 1024, 1024);
    transpose_h_kernel<<<((long)EE * FF) / 256, blk>>>(W1, W1t, EE, FF);   // dst [F][E]
    transpose_h_kernel<<<((long)FF * EE) / 256, blk>>>(W2, W2t, FF, EE);   // dst [E][F]

    // 1) QK projection: [8192,1024] x [2048,1024]^T -> QKh [8192,2048] half
    hgemm_kernel<128, true><<<dim3(2048 / 128, NTOK / 128, 1), gblk, SM128>>>(
        Xh, Wqk, QKh, EE, EE, EE, 2048,
        0, 0, 0, 0, 0, 0, 1, nullptr, nullptr, 0, 0, 0);

    // 2) Vt: per b: [1024,1024](Wvt) x [2048,1024](Xh_b)^T -> Vth[b][1024,2048] half
    hgemm_kernel<128, true><<<dim3(SS / 128, 1024 / 128, BB), gblk, SM128>>>(
        Wvt, Xh, Vth, EE, EE, EE, SS,
        0, 0, (long)SS * EE, 0, 1024L * SS, 0, 1, nullptr, nullptr, 0, 0, 0);

    // 3) scores + exp: per (b,h): Q[2048,64] x K[2048,64]^T -> att = exp(. - 12) half
    hgemm_kernel<128, true><<<dim3(SS / 128, SS / 128, BB * HH), gblk, SM128>>>(
        QKh, QKh + 1024, ATT, DD, 2048, 2048, SS,
        SSl * 2048, 64, SSl * 2048, 64, (long)HH * SSS, SSS, HH,
        nullptr, nullptr, 0, 0, 1);

    // 4) column sums (query axis) -> inv = 0.125/sum; fold into V
    colsum_kernel<<<dim3(SS / 512, BB * HH), blk>>>(ATT, INV);
    vscale_kernel<<<(int)(((long)BB * 1024 * SS / 2 + 255) / 256), blk>>>(Vth, INV);

    // 5) AV: per (b,h): att[2048,2048] x Vt'[64,2048]^T -> AVh[b*S+s][h*64+d]
    hgemm_kernel<64, true><<<dim3(1, SS / 128, BB * HH), gblk, SM64>>>(
        ATT, Vth, AVh, SS, SS, SS, EE,
        (long)HH * SSS, SSS, 1024L * SS, 64L * SS, SSl * EE, 64, HH,
        nullptr, nullptr, 0, 0, 0);

    // 6) WO: [8192,1024] x [1024,1024]^T + X -> Y fp32; LN -> VAf/VAh
    hgemm_kernel<128, false><<<dim3(EE / 128, NTOK / 128, 1), gblk, SM128>>>(
        AVh, Wot, Y, 1024, 1024, 1024, EE,
        0, 0, 0, 0, 0, 0, 1, nullptr, X, EE, 0, 0);
    layernorm_kernel<<<NTOK, blk>>>(Y, gamma, beta, VAf, VAh);

    // 7) FFN1: [8192,1024] x [4096,1024]^T + b1, relu -> H1h half
    hgemm_kernel<128, true><<<dim3(FF / 128, NTOK / 128, 1), gblk, SM128>>>(
        VAh, W1t, H1h, EE, EE, EE, FF,
        0, 0, 0, 0, 0, 0, 1, b1, nullptr, 0, 1, 0);

    // 8) FFN2: [8192,4096] x [1024,4096]^T + b2 + VAf -> Z fp32; LN -> out
    hgemm_kernel<128, false><<<dim3(EE / 128, NTOK / 128, 1), gblk, SM128>>>(
        H1h, W2t, Z, FF, FF, FF, EE,
        0, 0, 0, 0, 0, 0, 1, b2, VAf, EE, 0, 0);
    layernorm_kernel<<<NTOK, blk>>>(Z, gamma, beta, out, nullptr);
}

// round 7
// speedup vs baseline: 7.0888x; 1.2481x over previous
#include <cuda_runtime.h>
#include <cuda_fp16.h>
#include <cstdint>

#define BB 4
#define SS 2048
#define EE 1024
#define HH 16
#define DD 64
#define FF 4096
#define LN_EPS 1e-5f
#define NTOK (BB*SS)
#define EXP_SHIFT 12.0f

// ---------------- scratch (device globals) ----------------
__device__ __half g_Xh[(long)NTOK*EE];
__device__ __half g_Wqk[2048L*EE];          // rows: [Q(h*64+d) | K(h*64+d)], cols e
__device__ __half g_Wvt[1024L*EE];          // rows h*64+d, cols e
__device__ __half g_Wot[1024L*1024];        // rows e_out, cols hd
__device__ __half g_W1t[(long)FF*EE];       // rows f, cols e
__device__ __half g_W2t[(long)EE*FF];       // rows e, cols f
__device__ __half g_QKh[(long)NTOK*2048];   // [b*S+s][ Q: h*64+d , K: 1024+h*64+d ]
__device__ __half g_Vth[(long)BB*1024*SS];  // [b][h*64+d][t]
__device__ __half g_att[268435456L];        // [b,h][s][t]  unnormalized exp (0.5 GB)
__device__ float  g_part[64L*32*SS];        // partial col sums [z][by*2+warpM][t] (16 MB)
__device__ float  g_inv[(long)BB*HH*SS];    // 0.125 / colsum per (z,t)
__device__ __half g_AVh[(long)NTOK*EE];     // [b*S+s][h*64+d]
__device__ float  g_Y[(long)NTOK*EE];
__device__ float  g_VAf[(long)NTOK*EE];
__device__ __half g_VAh[(long)NTOK*EE];
__device__ __half g_H1h[(long)NTOK*FF];
__device__ float  g_Z[(long)NTOK*EE];

// ---------------- PTX helpers ----------------
__device__ __forceinline__ uint32_t smem_u32(const void* p) {
    uint32_t a;
    asm("{ .reg .u64 t; cvta.to.shared.u64 t, %1; cvt.u32.u64 %0, t; }" : "=r"(a) : "l"(p));
    return a;
}
__device__ __forceinline__ void cp16(uint32_t dst, const void* src) {
    asm volatile("cp.async.cg.shared.global [%0], [%1], 16;" :: "r"(dst), "l"(src));
}

// ---------------- HMMA f16 GEMM: C[M,N] = A[M,K] * B[N,K]^T ----------------
// A, B half, K-major. BM=128, BK=64, 128 threads = 4 warps (2m x 2n), warp 64xWN.
// 3-stage cp.async pipeline, one __syncthreads per k-iter.
// do_exp: C = exp(C - EXP_SHIFT) (half out) and per-(CTAy,warpM) column sums
// are written to part[] for the softmax normalization.
template<int BN, bool OUT_HALF>
__global__ __launch_bounds__(128)
void hgemm_kernel(const __half* __restrict__ A, const __half* __restrict__ B,
                  void* __restrict__ Cv, int K, int lda, int ldb, int ldc,
                  long sA1, long sA2, long sB1, long sB2, long sC1, long sC2, int Z2,
                  const float* __restrict__ bias, const float* __restrict__ residual,
                  int ldr, int do_relu, int do_exp, float* __restrict__ part)
{
    constexpr int BM = 128;
    constexpr int STG_A = BM * 128;       // bytes per A stage (128B = 64 halfs per row)
    constexpr int STG_B = BN * 128;
    constexpr int STG   = STG_A + STG_B;
    constexpr int WN = BN / 2;            // warp n extent
    constexpr int MT = 4;                 // m16 tiles per warp (64 rows)
    constexpr int NT = WN / 8;            // n8 tiles per warp

    extern __shared__ char smem_raw[];
    const uint32_t sb0   = smem_u32(smem_raw);
    const uint32_t sbase = (sb0 + 127u) & ~127u;

    const int tid  = threadIdx.x;
    const int lane = tid & 31;
    const int wid  = tid >> 5;
    const int wm   = (wid & 1) << 6;      // warp m offset (0, 64)
    const int wn   = (wid >> 1) * WN;     // warp n offset

    const int z  = blockIdx.z;
    const int z1 = z / Z2, z2 = z - z1 * Z2;
    A += z1 * sA1 + z2 * sA2;
    B += z1 * sB1 + z2 * sB2;
    const long coff = z1 * sC1 + z2 * sC2;
    const int m0 = blockIdx.y * BM;
    const int n0 = blockIdx.x * BN;

    float acc[MT][NT][4];
    #pragma unroll
    for (int i = 0; i < MT; i++)
        #pragma unroll
        for (int j = 0; j < NT; j++)
            #pragma unroll
            for (int k = 0; k < 4; k++) acc[i][j][k] = 0.0f;

    const int nK = K >> 6;

    auto load_stage = [&](int stg, int kt) {
        uint32_t sA = sbase + stg * STG;
        const char* Ab = (const char*)(A + (long)m0 * lda + kt * 64);
        #pragma unroll
        for (int idx = tid; idx < BM * 8; idx += 128) {
            int r = idx >> 3, c = (idx & 7) << 4;
            uint32_t off = (uint32_t)(r * 128 + c); off ^= (off >> 3) & 0x70;
            cp16(sA + off, Ab + (long)r * lda * 2 + c);
        }
        uint32_t sB = sbase + stg * STG + STG_A;
        const char* Bb = (const char*)(B + (long)n0 * ldb + kt * 64);
        #pragma unroll
        for (int idx = tid; idx < BN * 8; idx += 128) {
            int r = idx >> 3, c = (idx & 7) << 4;
            uint32_t off = (uint32_t)(r * 128 + c); off ^= (off >> 3) & 0x70;
            cp16(sB + off, Bb + (long)r * ldb * 2 + c);
        }
        asm volatile("cp.async.commit_group;" ::: "memory");
    };

    load_stage(0, 0);
    if (nK > 1) load_stage(1, 1);

    for (int i = 0; i < nK; i++) {
        if (i + 1 < nK) asm volatile("cp.async.wait_group 1;" ::: "memory");
        else            asm volatile("cp.async.wait_group 0;" ::: "memory");
        __syncthreads();
        if (i + 2 < nK) {
            int st = (i + 2) % 3;
            load_stage(st, i + 2);
        }

        const uint32_t sA = sbase + (i % 3) * STG;
        const uint32_t sB = sA + STG_A;
        #pragma unroll
        for (int ks = 0; ks < 4; ks++) {
            uint32_t a[MT][4];
            #pragma unroll
            for (int mt = 0; mt < MT; mt++) {
                int m = wm + (mt << 4) + (lane & 15);
                uint32_t off = (uint32_t)((m << 7) + (ks << 5) + ((lane >> 4) << 4));
                off ^= (off >> 3) & 0x70;
                asm volatile("ldmatrix.sync.aligned.m8n8.x4.shared.b16 {%0,%1,%2,%3}, [%4];"
                    : "=r"(a[mt][0]), "=r"(a[mt][1]), "=r"(a[mt][2]), "=r"(a[mt][3])
                    : "r"(sA + off));
            }
            uint32_t b[NT][2];
            #pragma unroll
            for (int p = 0; p < NT / 2; p++) {
                int quad = lane >> 3;
                int n = wn + (p << 4) + ((quad & 2) << 2) + (lane & 7);
                uint32_t off = (uint32_t)((n << 7) + (ks << 5) + ((quad & 1) << 4));
                off ^= (off >> 3) & 0x70;
                asm volatile("ldmatrix.sync.aligned.m8n8.x4.shared.b16 {%0,%1,%2,%3}, [%4];"
                    : "=r"(b[2*p][0]), "=r"(b[2*p][1]), "=r"(b[2*p+1][0]), "=r"(b[2*p+1][1])
                    : "r"(sB + off));
            }
            #pragma unroll
            for (int mt = 0; mt < MT; mt++)
                #pragma unroll
                for (int nt = 0; nt < NT; nt++)
                    asm volatile("mma.sync.aligned.m16n8k16.row.col.f32.f16.f16.f32 "
                        "{%0,%1,%2,%3}, {%4,%5,%6,%7}, {%8,%9}, {%0,%1,%2,%3};"
                        : "+f"(acc[mt][nt][0]), "+f"(acc[mt][nt][1]),
                          "+f"(acc[mt][nt][2]), "+f"(acc[mt][nt][3])
                        : "r"(a[mt][0]), "r"(a[mt][1]), "r"(a[mt][2]), "r"(a[mt][3]),
                          "r"(b[nt][0]), "r"(b[nt][1]));
        }
    }

    // -------- epilogue: register fragments -> global (fused bias/residual/relu/exp) --
    const int mrow = lane >> 2;
    const int ncol = (lane & 3) << 1;
    float cs[NT][2];
    #pragma unroll
    for (int j = 0; j < NT; j++) { cs[j][0] = 0.0f; cs[j][1] = 0.0f; }

    #pragma unroll
    for (int mt = 0; mt < MT; mt++) {
        #pragma unroll
        for (int nt = 0; nt < NT; nt++) {
            long gm = m0 + wm + (mt << 4) + mrow;
            int  gn = n0 + wn + (nt << 3) + ncol;
            float v0 = acc[mt][nt][0], v1 = acc[mt][nt][1];
            float v2 = acc[mt][nt][2], v3 = acc[mt][nt][3];
            if (bias) {
                float b0 = bias[gn], b1 = bias[gn + 1];
                v0 += b0; v1 += b1; v2 += b0; v3 += b1;
            }
            if (residual) {
                const float2 r0 = *(const float2*)(residual + gm * ldr + gn);
                const float2 r1 = *(const float2*)(residual + (gm + 8) * ldr + gn);
                v0 += r0.x; v1 += r0.y; v2 += r1.x; v3 += r1.y;
            }
            if (do_relu) {
                v0 = fmaxf(v0, 0.0f); v1 = fmaxf(v1, 0.0f);
                v2 = fmaxf(v2, 0.0f); v3 = fmaxf(v3, 0.0f);
            }
            if (do_exp) {
                v0 = fminf(__expf(v0 - EXP_SHIFT), 60000.0f);
                v1 = fminf(__expf(v1 - EXP_SHIFT), 60000.0f);
                v2 = fminf(__expf(v2 - EXP_SHIFT), 60000.0f);
                v3 = fminf(__expf(v3 - EXP_SHIFT), 60000.0f);
                cs[nt][0] += v0 + v2;
                cs[nt][1] += v1 + v3;
            }
            if (OUT_HALF) {
                *(__half2*)((__half*)Cv + coff + gm * ldc + gn)       = __floats2half2_rn(v0, v1);
                *(__half2*)((__half*)Cv + coff + (gm + 8) * ldc + gn) = __floats2half2_rn(v2, v3);
            } else {
                *(float2*)((float*)Cv + coff + gm * ldc + gn)       = make_float2(v0, v1);
                *(float2*)((float*)Cv + coff + (gm + 8) * ldc + gn) = make_float2(v2, v3);
            }
        }
    }

    if (do_exp) {
        // reduce 8 mrow lanes per column pair, then lanes 0..3 store partials
        #pragma unroll
        for (int nt = 0; nt < NT; nt++) {
            float c0 = cs[nt][0], c1 = cs[nt][1];
            #pragma unroll
            for (int o = 4; o <= 16; o <<= 1) {
                c0 += __shfl_xor_sync(0xffffffffu, c0, o);
                c1 += __shfl_xor_sync(0xffffffffu, c1, o);
            }
            if ((lane >> 2) == 0) {
                int gn = n0 + wn + (nt << 3) + ncol;
                long idx = (((long)z * gridDim.y + blockIdx.y) * 2 + (wid & 1)) * SS + gn;
                part[idx]     = c0;
                part[idx + 1] = c1;
            }
        }
    }
}

// ---------------- conversion / packing kernels ----------------
__global__ __launch_bounds__(256) void f2h_kernel(const float* __restrict__ s,
                                                  __half* __restrict__ d, long n) {
    long i = (long)blockIdx.x * 256 + threadIdx.x;
    if (i < n) d[i] = __float2half(s[i]);
}
__global__ __launch_bounds__(256) void pack_qk_kernel(const float* __restrict__ WQ,
                                                      const float* __restrict__ WK,
                                                      __half* __restrict__ dst) {
    long i = (long)blockIdx.x * 256 + threadIdx.x;   // over 2048*1024
    int n = (int)(i >> 10), e = (int)(i & 1023);
    const float* W = (n < 1024) ? WQ : WK;
    int hd = n & 1023; int h = hd >> 6, d = hd & 63;
    dst[i] = __float2half(W[((long)h * 1024 + e) * 64 + d]);
}
__global__ __launch_bounds__(256) void pack_vt_kernel(const float* __restrict__ WV,
                                                      __half* __restrict__ dst) {
    long i = (long)blockIdx.x * 256 + threadIdx.x;   // over 1024*1024
    int n = (int)(i >> 10), e = (int)(i & 1023);
    int h = n >> 6, d = n & 63;
    dst[i] = __float2half(WV[((long)h * 1024 + e) * 64 + d]);
}
__global__ __launch_bounds__(256) void transpose_h_kernel(const float* __restrict__ src,
                                                          __half* __restrict__ dst,
                                                          int R, int C) {
    long i = (long)blockIdx.x * 256 + threadIdx.x;   // i = c*R + r
    if (i >= (long)R * C) return;
    int c = (int)(i / R), r = (int)(i % R);
    dst[i] = __float2half(src[(long)r * C + c]);
}

// ---------------- reduce partial col sums -> inv = 0.125/sum ----------------
__global__ __launch_bounds__(256) void reduce_inv_kernel(const float* __restrict__ part,
                                                         float* __restrict__ inv) {
    long z = blockIdx.y;
    int  t = blockIdx.x * 256 + threadIdx.x;
    const float* p = part + (z * 32) * (long)SS + t;
    float s = 0.0f;
    #pragma unroll
    for (int j = 0; j < 32; j++) s += p[(long)j * SS];
    inv[z * (long)SS + t] = 0.125f / s;
}

// ---------------- scale Vth rows by inv (folds softmax normalization) --------
__global__ __launch_bounds__(256) void vscale_kernel(__half* __restrict__ v,
                                                     const float* __restrict__ inv) {
    long i2 = (long)blockIdx.x * 256 + threadIdx.x;     // over elements/2
    long i  = i2 * 2;
    if (i >= (long)BB * 1024 * SS) return;
    int t  = (int)(i & (SS - 1));
    int hd = (int)((i >> 11) & 1023);
    int b  = (int)(i >> 21);
    const float* ip = inv + ((long)(b * HH + (hd >> 6))) * SS + t;
    __half2* p = (__half2*)(v + i);
    float2 f = __half22float2(*p);
    f.x *= ip[0]; f.y *= ip[1];
    *p = __floats2half2_rn(f.x, f.y);
}

// ---------------- layernorm (E=1024), optional half copy ----------------
__global__ __launch_bounds__(256)
void layernorm_kernel(const float* __restrict__ x, const float* __restrict__ gamma,
                      const float* __restrict__ beta, float* __restrict__ outf,
                      __half* __restrict__ outh) {
    long row = blockIdx.x;
    const float* p = x + row * (long)EE;
    const int tid = threadIdx.x, lane = tid & 31, warp = tid >> 5;

    float v[4]; float s = 0.0f;
    #pragma unroll
    for (int i = 0; i < 4; i++) { v[i] = p[tid + i * 256]; s += v[i]; }
    __shared__ float red1[8], red2[8];
    #pragma unroll
    for (int o = 16; o > 0; o >>= 1) s += __shfl_xor_sync(0xffffffffu, s, o);
    if (lane == 0) red1[warp] = s;
    __syncthreads();
    float tot = red1[0];
    #pragma unroll
    for (int i = 1; i < 8; i++) tot += red1[i];
    float mu = tot * (1.0f / EE);

    float q = 0.0f;
    #pragma unroll
    for (int i = 0; i < 4; i++) { float d = v[i] - mu; q += d * d; }
    #pragma unroll
    for (int o = 16; o > 0; o >>= 1) q += __shfl_xor_sync(0xffffffffu, q, o);
    if (lane == 0) red2[warp] = q;
    __syncthreads();
    float qt = red2[0];
    #pragma unroll
    for (int i = 1; i < 8; i++) qt += red2[i];
    float rstd = rsqrtf(qt * (1.0f / EE) + LN_EPS);

    #pragma unroll
    for (int i = 0; i < 4; i++) {
        int col = tid + i * 256;
        float y = (v[i] - mu) * rstd * gamma[col] + beta[col];
        outf[row * (long)EE + col] = y;
        if (outh) outh[row * (long)EE + col] = __float2half(y);
    }
}

// ---------------- launcher ----------------
extern "C" void kernel_launch(void* const* d_in, const int* in_sizes, int n_in,
                              void* d_out, int out_size)
{
    const float* X     = (const float*)d_in[0];
    const float* WQ    = (const float*)d_in[1];
    const float* WK    = (const float*)d_in[2];
    const float* WV    = (const float*)d_in[3];
    const float* WO    = (const float*)d_in[4];
    const float* gamma = (const float*)d_in[5];
    const float* beta  = (const float*)d_in[6];
    const float* W1    = (const float*)d_in[7];
    const float* b1    = (const float*)d_in[8];
    const float* W2    = (const float*)d_in[9];
    const float* b2    = (const float*)d_in[10];
    float* out = (float*)d_out;

    __half *Xh, *Wqk, *Wvt, *Wot, *W1t, *W2t, *QKh, *Vth, *ATT, *AVh, *VAh, *H1h;
    float *PART, *INV, *Y, *VAf, *Z;
    cudaGetSymbolAddress((void**)&Xh,  g_Xh);
    cudaGetSymbolAddress((void**)&Wqk, g_Wqk);
    cudaGetSymbolAddress((void**)&Wvt, g_Wvt);
    cudaGetSymbolAddress((void**)&Wot, g_Wot);
    cudaGetSymbolAddress((void**)&W1t, g_W1t);
    cudaGetSymbolAddress((void**)&W2t, g_W2t);
    cudaGetSymbolAddress((void**)&QKh, g_QKh);
    cudaGetSymbolAddress((void**)&Vth, g_Vth);
    cudaGetSymbolAddress((void**)&ATT, g_att);
    cudaGetSymbolAddress((void**)&PART, g_part);
    cudaGetSymbolAddress((void**)&INV, g_inv);
    cudaGetSymbolAddress((void**)&AVh, g_AVh);
    cudaGetSymbolAddress((void**)&Y,   g_Y);
    cudaGetSymbolAddress((void**)&VAf, g_VAf);
    cudaGetSymbolAddress((void**)&VAh, g_VAh);
    cudaGetSymbolAddress((void**)&H1h, g_H1h);
    cudaGetSymbolAddress((void**)&Z,   g_Z);

    const int SM128 = 3 * (128 * 128 + 128 * 128) + 256;   // 98560 bytes
    const int SM64  = 3 * (128 * 128 +  64 * 128) + 256;   // 73984 bytes
    cudaFuncSetAttribute(hgemm_kernel<128, true>,  cudaFuncAttributeMaxDynamicSharedMemorySize, SM128);
    cudaFuncSetAttribute(hgemm_kernel<128, false>, cudaFuncAttributeMaxDynamicSharedMemorySize, SM128);
    cudaFuncSetAttribute(hgemm_kernel<64,  true>,  cudaFuncAttributeMaxDynamicSharedMemorySize, SM64);

    const long SSl = SS, SSS = SSl * SSl;
    dim3 blk(256);
    dim3 gblk(128);

    // 0) conversions / packing
    f2h_kernel<<<(NTOK * (long)EE) / 256, blk>>>(X, Xh, (long)NTOK * EE);
    pack_qk_kernel<<<(2048L * EE) / 256, blk>>>(WQ, WK, Wqk);
    pack_vt_kernel<<<(1024L * EE) / 256, blk>>>(WV, Wvt);
    transpose_h_kernel<<<(1024L * 1024) / 256, blk>>>(WO, Wot, 1024, 1024);
    transpose_h_kernel<<<((long)EE * FF) / 256, blk>>>(W1, W1t, EE, FF);   // dst [F][E]
    transpose_h_kernel<<<((long)FF * EE) / 256, blk>>>(W2, W2t, FF, EE);   // dst [E][F]

    // 1) QK projection: [8192,1024] x [2048,1024]^T -> QKh [8192,2048] half
    hgemm_kernel<128, true><<<dim3(2048 / 128, NTOK / 128, 1), gblk, SM128>>>(
        Xh, Wqk, QKh, EE, EE, EE, 2048,
        0, 0, 0, 0, 0, 0, 1, nullptr, nullptr, 0, 0, 0, nullptr);

    // 2) Vt: per b: [1024,1024](Wvt) x [2048,1024](Xh_b)^T -> Vth[b][1024,2048] half
    hgemm_kernel<128, true><<<dim3(SS / 128, 1024 / 128, BB), gblk, SM128>>>(
        Wvt, Xh, Vth, EE, EE, EE, SS,
        0, 0, (long)SS * EE, 0, 1024L * SS, 0, 1, nullptr, nullptr, 0, 0, 0, nullptr);

    // 3) scores + exp + partial col sums: Q[2048,64] x K[2048,64]^T -> att half
    hgemm_kernel<128, true><<<dim3(SS / 128, SS / 128, BB * HH), gblk, SM128>>>(
        QKh, QKh + 1024, ATT, DD, 2048, 2048, SS,
        SSl * 2048, 64, SSl * 2048, 64, (long)HH * SSS, SSS, HH,
        nullptr, nullptr, 0, 0, 1, PART);

    // 4) reduce partials -> inv = 0.125/sum; fold into V
    reduce_inv_kernel<<<dim3(SS / 256, BB * HH), blk>>>(PART, INV);
    vscale_kernel<<<(int)(((long)BB * 1024 * SS / 2 + 255) / 256), blk>>>(Vth, INV);

    // 5) AV: per (b,h): att[2048,2048] x Vt'[64,2048]^T -> AVh[b*S+s][h*64+d]
    hgemm_kernel<64, true><<<dim3(1, SS / 128, BB * HH), gblk, SM64>>>(
        ATT, Vth, AVh, SS, SS, SS, EE,
        (long)HH * SSS, SSS, 1024L * SS, 64L * SS, SSl * EE, 64, HH,
        nullptr, nullptr, 0, 0, 0, nullptr);

    // 6) WO: [8192,1024] x [1024,1024]^T + X -> Y fp32; LN -> VAf/VAh
    hgemm_kernel<128, false><<<dim3(EE / 128, NTOK / 128, 1), gblk, SM128>>>(
        AVh, Wot, Y, 1024, 1024, 1024, EE,
        0, 0, 0, 0, 0, 0, 1, nullptr, X, EE, 0, 0, nullptr);
    layernorm_kernel<<<NTOK, blk>>>(Y, gamma, beta, VAf, VAh);

    // 7) FFN1: [8192,1024] x [4096,1024]^T + b1, relu -> H1h half
    hgemm_kernel<128, true><<<dim3(FF / 128, NTOK / 128, 1), gblk, SM128>>>(
        VAh, W1t, H1h, EE, EE, EE, FF,
        0, 0, 0, 0, 0, 0, 1, b1, nullptr, 0, 1, 0, nullptr);

    // 8) FFN2: [8192,4096] x [1024,4096]^T + b2 + VAf -> Z fp32; LN -> out
    hgemm_kernel<128, false><<<dim3(EE / 128, NTOK / 128, 1), gblk, SM128>>>(
        H1h, W2t, Z, FF, FF, FF, EE,
        0, 0, 0, 0, 0, 0, 1, b2, VAf, EE, 0, 0, nullptr);
    layernorm_kernel<<<NTOK, blk>>>(Z, gamma, beta, out, nullptr);
}

// round 8
// speedup vs baseline: 7.6097x; 1.0735x over previous
#include <cuda_runtime.h>
#include <cuda_fp16.h>
#include <cstdint>

#define BB 4
#define SS 2048
#define EE 1024
#define HH 16
#define DD 64
#define FF 4096
#define LN_EPS 1e-5f
#define NTOK (BB*SS)
#define EXP_SHIFT 12.0f

// ---------------- scratch (device globals) ----------------
__device__ __half g_Xh[(long)NTOK*EE];
__device__ __half g_Wqk[2048L*EE];          // rows: [Q(h*64+d) | K(h*64+d)], cols e
__device__ __half g_Wvt[1024L*EE];          // rows h*64+d, cols e
__device__ __half g_Wot[1024L*1024];        // rows e_out, cols hd
__device__ __half g_W1t[(long)FF*EE];       // rows f, cols e
__device__ __half g_W2t[(long)EE*FF];       // rows e, cols f
__device__ __half g_QKh[(long)NTOK*2048];   // [b*S+s][ Q: h*64+d , K: 1024+h*64+d ]
__device__ __half g_Vth[(long)BB*1024*SS];  // [b][h*64+d][t]
__device__ __half g_att[268435456L];        // [b,h][s][t]  unnormalized exp (0.5 GB)
__device__ float  g_part[64L*32*SS];        // partial col sums [z][by*2+warpM][t] (16 MB)
__device__ float  g_inv[(long)BB*HH*SS];    // 0.125 / colsum per (z,t)
__device__ __half g_AVh[(long)NTOK*EE];     // [b*S+s][h*64+d]
__device__ float  g_Y[(long)NTOK*EE];
__device__ float  g_VAf[(long)NTOK*EE];
__device__ __half g_VAh[(long)NTOK*EE];
__device__ __half g_H1h[(long)NTOK*FF];
__device__ float  g_Z[(long)NTOK*EE];

// ---------------- PTX helpers ----------------
__device__ __forceinline__ uint32_t smem_u32(const void* p) {
    uint32_t a;
    asm("{ .reg .u64 t; cvta.to.shared.u64 t, %1; cvt.u32.u64 %0, t; }" : "=r"(a) : "l"(p));
    return a;
}
__device__ __forceinline__ void cp16(uint32_t dst, const void* src) {
    asm volatile("cp.async.cg.shared.global [%0], [%1], 16;" :: "r"(dst), "l"(src));
}

// ---------------- HMMA f16 GEMM: C[M,N] = A[M,K] * B[N,K]^T ----------------
// A, B half, K-major. BM=128, BK=64, 128 threads = 4 warps (2m x 2n), warp 64xWN.
// 3-stage cp.async pipeline, one __syncthreads per k-iter.
template<int BN, bool OUT_HALF>
__global__ __launch_bounds__(128)
void hgemm_kernel(const __half* __restrict__ A, const __half* __restrict__ B,
                  void* __restrict__ Cv, int K, int lda, int ldb, int ldc,
                  long sA1, long sA2, long sB1, long sB2, long sC1, long sC2, int Z2,
                  const float* __restrict__ bias, const float* __restrict__ residual,
                  int ldr, int do_relu, int do_exp, float* __restrict__ part)
{
    constexpr int BM = 128;
    constexpr int STG_A = BM * 128;       // bytes per A stage (128B = 64 halfs per row)
    constexpr int STG_B = BN * 128;
    constexpr int STG   = STG_A + STG_B;
    constexpr int WN = BN / 2;            // warp n extent
    constexpr int MT = 4;                 // m16 tiles per warp (64 rows)
    constexpr int NT = WN / 8;            // n8 tiles per warp

    extern __shared__ char smem_raw[];
    const uint32_t sb0   = smem_u32(smem_raw);
    const uint32_t sbase = (sb0 + 127u) & ~127u;

    const int tid  = threadIdx.x;
    const int lane = tid & 31;
    const int wid  = tid >> 5;
    const int wm   = (wid & 1) << 6;      // warp m offset (0, 64)
    const int wn   = (wid >> 1) * WN;     // warp n offset

    const int z  = blockIdx.z;
    const int z1 = z / Z2, z2 = z - z1 * Z2;
    A += z1 * sA1 + z2 * sA2;
    B += z1 * sB1 + z2 * sB2;
    const long coff = z1 * sC1 + z2 * sC2;
    const int m0 = blockIdx.y * BM;
    const int n0 = blockIdx.x * BN;

    float acc[MT][NT][4];
    #pragma unroll
    for (int i = 0; i < MT; i++)
        #pragma unroll
        for (int j = 0; j < NT; j++)
            #pragma unroll
            for (int k = 0; k < 4; k++) acc[i][j][k] = 0.0f;

    const int nK = K >> 6;

    auto load_stage = [&](int stg, int kt) {
        uint32_t sA = sbase + stg * STG;
        const char* Ab = (const char*)(A + (long)m0 * lda + kt * 64);
        #pragma unroll
        for (int idx = tid; idx < BM * 8; idx += 128) {
            int r = idx >> 3, c = (idx & 7) << 4;
            uint32_t off = (uint32_t)(r * 128 + c); off ^= (off >> 3) & 0x70;
            cp16(sA + off, Ab + (long)r * lda * 2 + c);
        }
        uint32_t sB = sbase + stg * STG + STG_A;
        const char* Bb = (const char*)(B + (long)n0 * ldb + kt * 64);
        #pragma unroll
        for (int idx = tid; idx < BN * 8; idx += 128) {
            int r = idx >> 3, c = (idx & 7) << 4;
            uint32_t off = (uint32_t)(r * 128 + c); off ^= (off >> 3) & 0x70;
            cp16(sB + off, Bb + (long)r * ldb * 2 + c);
        }
        asm volatile("cp.async.commit_group;" ::: "memory");
    };

    load_stage(0, 0);
    if (nK > 1) load_stage(1, 1);

    for (int i = 0; i < nK; i++) {
        if (i + 1 < nK) asm volatile("cp.async.wait_group 1;" ::: "memory");
        else            asm volatile("cp.async.wait_group 0;" ::: "memory");
        __syncthreads();
        if (i + 2 < nK) {
            int st = (i + 2) % 3;
            load_stage(st, i + 2);
        }

        const uint32_t sA = sbase + (i % 3) * STG;
        const uint32_t sB = sA + STG_A;
        #pragma unroll
        for (int ks = 0; ks < 4; ks++) {
            uint32_t a[MT][4];
            #pragma unroll
            for (int mt = 0; mt < MT; mt++) {
                int m = wm + (mt << 4) + (lane & 15);
                uint32_t off = (uint32_t)((m << 7) + (ks << 5) + ((lane >> 4) << 4));
                off ^= (off >> 3) & 0x70;
                asm volatile("ldmatrix.sync.aligned.m8n8.x4.shared.b16 {%0,%1,%2,%3}, [%4];"
                    : "=r"(a[mt][0]), "=r"(a[mt][1]), "=r"(a[mt][2]), "=r"(a[mt][3])
                    : "r"(sA + off));
            }
            uint32_t b[NT][2];
            #pragma unroll
            for (int p = 0; p < NT / 2; p++) {
                int quad = lane >> 3;
                int n = wn + (p << 4) + ((quad & 2) << 2) + (lane & 7);
                uint32_t off = (uint32_t)((n << 7) + (ks << 5) + ((quad & 1) << 4));
                off ^= (off >> 3) & 0x70;
                asm volatile("ldmatrix.sync.aligned.m8n8.x4.shared.b16 {%0,%1,%2,%3}, [%4];"
                    : "=r"(b[2*p][0]), "=r"(b[2*p][1]), "=r"(b[2*p+1][0]), "=r"(b[2*p+1][1])
                    : "r"(sB + off));
            }
            #pragma unroll
            for (int mt = 0; mt < MT; mt++)
                #pragma unroll
                for (int nt = 0; nt < NT; nt++)
                    asm volatile("mma.sync.aligned.m16n8k16.row.col.f32.f16.f16.f32 "
                        "{%0,%1,%2,%3}, {%4,%5,%6,%7}, {%8,%9}, {%0,%1,%2,%3};"
                        : "+f"(acc[mt][nt][0]), "+f"(acc[mt][nt][1]),
                          "+f"(acc[mt][nt][2]), "+f"(acc[mt][nt][3])
                        : "r"(a[mt][0]), "r"(a[mt][1]), "r"(a[mt][2]), "r"(a[mt][3]),
                          "r"(b[nt][0]), "r"(b[nt][1]));
        }
    }

    // -------- epilogue: register fragments -> global (fused bias/residual/relu/exp) --
    const int mrow = lane >> 2;
    const int ncol = (lane & 3) << 1;
    float cs[NT][2];
    #pragma unroll
    for (int j = 0; j < NT; j++) { cs[j][0] = 0.0f; cs[j][1] = 0.0f; }

    #pragma unroll
    for (int mt = 0; mt < MT; mt++) {
        #pragma unroll
        for (int nt = 0; nt < NT; nt++) {
            long gm = m0 + wm + (mt << 4) + mrow;
            int  gn = n0 + wn + (nt << 3) + ncol;
            float v0 = acc[mt][nt][0], v1 = acc[mt][nt][1];
            float v2 = acc[mt][nt][2], v3 = acc[mt][nt][3];
            if (bias) {
                float b0 = bias[gn], b1 = bias[gn + 1];
                v0 += b0; v1 += b1; v2 += b0; v3 += b1;
            }
            if (residual) {
                const float2 r0 = *(const float2*)(residual + gm * ldr + gn);
                const float2 r1 = *(const float2*)(residual + (gm + 8) * ldr + gn);
                v0 += r0.x; v1 += r0.y; v2 += r1.x; v3 += r1.y;
            }
            if (do_relu) {
                v0 = fmaxf(v0, 0.0f); v1 = fmaxf(v1, 0.0f);
                v2 = fmaxf(v2, 0.0f); v3 = fmaxf(v3, 0.0f);
            }
            if (do_exp) {
                v0 = fminf(__expf(v0 - EXP_SHIFT), 60000.0f);
                v1 = fminf(__expf(v1 - EXP_SHIFT), 60000.0f);
                v2 = fminf(__expf(v2 - EXP_SHIFT), 60000.0f);
                v3 = fminf(__expf(v3 - EXP_SHIFT), 60000.0f);
                cs[nt][0] += v0 + v2;
                cs[nt][1] += v1 + v3;
            }
            if (OUT_HALF) {
                *(__half2*)((__half*)Cv + coff + gm * ldc + gn)       = __floats2half2_rn(v0, v1);
                *(__half2*)((__half*)Cv + coff + (gm + 8) * ldc + gn) = __floats2half2_rn(v2, v3);
            } else {
                *(float2*)((float*)Cv + coff + gm * ldc + gn)       = make_float2(v0, v1);
                *(float2*)((float*)Cv + coff + (gm + 8) * ldc + gn) = make_float2(v2, v3);
            }
        }
    }

    if (do_exp) {
        #pragma unroll
        for (int nt = 0; nt < NT; nt++) {
            float c0 = cs[nt][0], c1 = cs[nt][1];
            #pragma unroll
            for (int o = 4; o <= 16; o <<= 1) {
                c0 += __shfl_xor_sync(0xffffffffu, c0, o);
                c1 += __shfl_xor_sync(0xffffffffu, c1, o);
            }
            if ((lane >> 2) == 0) {
                int gn = n0 + wn + (nt << 3) + ncol;
                long idx = (((long)z * gridDim.y + blockIdx.y) * 2 + (wid & 1)) * SS + gn;
                part[idx]     = c0;
                part[idx + 1] = c1;
            }
        }
    }
}

// ---------------- conversion / packing kernels ----------------
__global__ __launch_bounds__(256) void f2h_kernel(const float4* __restrict__ s,
                                                  __half2* __restrict__ d, long n4) {
    long i = (long)blockIdx.x * 256 + threadIdx.x;
    if (i < n4) {
        float4 v = s[i];
        d[i * 2]     = __floats2half2_rn(v.x, v.y);
        d[i * 2 + 1] = __floats2half2_rn(v.z, v.w);
    }
}
// pack W[h][e][d] (h: [1024,64] slab) -> dst[(h*64+d)][e]  (tiled transpose)
__global__ __launch_bounds__(256) void pack_w_kernel(const float* __restrict__ W,
                                                     __half* __restrict__ dst) {
    __shared__ float tile[32][33];
    int h  = blockIdx.z;
    int eb = blockIdx.y * 32, db = blockIdx.x * 32;
    const float* Wh = W + (long)h * EE * DD;
    #pragma unroll
    for (int dy = 0; dy < 32; dy += 8)
        tile[threadIdx.y + dy][threadIdx.x] =
            Wh[(long)(eb + threadIdx.y + dy) * DD + db + threadIdx.x];
    __syncthreads();
    #pragma unroll
    for (int dy = 0; dy < 32; dy += 8)
        dst[(long)(h * DD + db + threadIdx.y + dy) * EE + eb + threadIdx.x] =
            __float2half(tile[threadIdx.x][threadIdx.y + dy]);
}
// dst[c][r] = src[r][c], tiled (R, C multiples of 32)
__global__ __launch_bounds__(256) void transpose_h_kernel(const float* __restrict__ src,
                                                          __half* __restrict__ dst,
                                                          int R, int C) {
    __shared__ float tile[32][33];
    int rb = blockIdx.y * 32, cb = blockIdx.x * 32;
    #pragma unroll
    for (int dy = 0; dy < 32; dy += 8)
        tile[threadIdx.y + dy][threadIdx.x] =
            src[(long)(rb + threadIdx.y + dy) * C + cb + threadIdx.x];
    __syncthreads();
    #pragma unroll
    for (int dy = 0; dy < 32; dy += 8)
        dst[(long)(cb + threadIdx.y + dy) * R + rb + threadIdx.x] =
            __float2half(tile[threadIdx.x][threadIdx.y + dy]);
}

// ---------------- reduce partial col sums -> inv = 0.125/sum ----------------
__global__ __launch_bounds__(256) void reduce_inv_kernel(const float* __restrict__ part,
                                                         float* __restrict__ inv) {
    long z = blockIdx.y;
    int  t = blockIdx.x * 256 + threadIdx.x;
    const float* p = part + (z * 32) * (long)SS + t;
    float s = 0.0f;
    #pragma unroll
    for (int j = 0; j < 32; j++) s += p[(long)j * SS];
    inv[z * (long)SS + t] = 0.125f / s;
}

// ---------------- scale Vth rows by inv (folds softmax normalization) --------
__global__ __launch_bounds__(256) void vscale_kernel(__half* __restrict__ v,
                                                     const float* __restrict__ inv) {
    long i2 = (long)blockIdx.x * 256 + threadIdx.x;     // over elements/2
    long i  = i2 * 2;
    if (i >= (long)BB * 1024 * SS) return;
    int t  = (int)(i & (SS - 1));
    int hd = (int)((i >> 11) & 1023);
    int b  = (int)(i >> 21);
    const float* ip = inv + ((long)(b * HH + (hd >> 6))) * SS + t;
    __half2* p = (__half2*)(v + i);
    float2 f = __half22float2(*p);
    f.x *= ip[0]; f.y *= ip[1];
    *p = __floats2half2_rn(f.x, f.y);
}

// ---------------- layernorm (E=1024), optional half copy ----------------
__global__ __launch_bounds__(256)
void layernorm_kernel(const float* __restrict__ x, const float* __restrict__ gamma,
                      const float* __restrict__ beta, float* __restrict__ outf,
                      __half* __restrict__ outh) {
    long row = blockIdx.x;
    const float* p = x + row * (long)EE;
    const int tid = threadIdx.x, lane = tid & 31, warp = tid >> 5;

    float v[4]; float s = 0.0f;
    #pragma unroll
    for (int i = 0; i < 4; i++) { v[i] = p[tid + i * 256]; s += v[i]; }
    __shared__ float red1[8], red2[8];
    #pragma unroll
    for (int o = 16; o > 0; o >>= 1) s += __shfl_xor_sync(0xffffffffu, s, o);
    if (lane == 0) red1[warp] = s;
    __syncthreads();
    float tot = red1[0];
    #pragma unroll
    for (int i = 1; i < 8; i++) tot += red1[i];
    float mu = tot * (1.0f / EE);

    float q = 0.0f;
    #pragma unroll
    for (int i = 0; i < 4; i++) { float d = v[i] - mu; q += d * d; }
    #pragma unroll
    for (int o = 16; o > 0; o >>= 1) q += __shfl_xor_sync(0xffffffffu, q, o);
    if (lane == 0) red2[warp] = q;
    __syncthreads();
    float qt = red2[0];
    #pragma unroll
    for (int i = 1; i < 8; i++) qt += red2[i];
    float rstd = rsqrtf(qt * (1.0f / EE) + LN_EPS);

    #pragma unroll
    for (int i = 0; i < 4; i++) {
        int col = tid + i * 256;
        float y = (v[i] - mu) * rstd * gamma[col] + beta[col];
        outf[row * (long)EE + col] = y;
        if (outh) outh[row * (long)EE + col] = __float2half(y);
    }
}

// ---------------- launcher ----------------
extern "C" void kernel_launch(void* const* d_in, const int* in_sizes, int n_in,
                              void* d_out, int out_size)
{
    const float* X     = (const float*)d_in[0];
    const float* WQ    = (const float*)d_in[1];
    const float* WK    = (const float*)d_in[2];
    const float* WV    = (const float*)d_in[3];
    const float* WO    = (const float*)d_in[4];
    const float* gamma = (const float*)d_in[5];
    const float* beta  = (const float*)d_in[6];
    const float* W1    = (const float*)d_in[7];
    const float* b1    = (const float*)d_in[8];
    const float* W2    = (const float*)d_in[9];
    const float* b2    = (const float*)d_in[10];
    float* out = (float*)d_out;

    __half *Xh, *Wqk, *Wvt, *Wot, *W1t, *W2t, *QKh, *Vth, *ATT, *AVh, *VAh, *H1h;
    float *PART, *INV, *Y, *VAf, *Z;
    cudaGetSymbolAddress((void**)&Xh,  g_Xh);
    cudaGetSymbolAddress((void**)&Wqk, g_Wqk);
    cudaGetSymbolAddress((void**)&Wvt, g_Wvt);
    cudaGetSymbolAddress((void**)&Wot, g_Wot);
    cudaGetSymbolAddress((void**)&W1t, g_W1t);
    cudaGetSymbolAddress((void**)&W2t, g_W2t);
    cudaGetSymbolAddress((void**)&QKh, g_QKh);
    cudaGetSymbolAddress((void**)&Vth, g_Vth);
    cudaGetSymbolAddress((void**)&ATT, g_att);
    cudaGetSymbolAddress((void**)&PART, g_part);
    cudaGetSymbolAddress((void**)&INV, g_inv);
    cudaGetSymbolAddress((void**)&AVh, g_AVh);
    cudaGetSymbolAddress((void**)&Y,   g_Y);
    cudaGetSymbolAddress((void**)&VAf, g_VAf);
    cudaGetSymbolAddress((void**)&VAh, g_VAh);
    cudaGetSymbolAddress((void**)&H1h, g_H1h);
    cudaGetSymbolAddress((void**)&Z,   g_Z);

    // side stream + fork/join events (created once, on the correctness call)
    static cudaStream_t side = nullptr;
    static cudaEvent_t evFork = nullptr, evJoin = nullptr;
    if (!side) {
        cudaStreamCreateWithFlags(&side, cudaStreamNonBlocking);
        cudaEventCreateWithFlags(&evFork, cudaEventDisableTiming);
        cudaEventCreateWithFlags(&evJoin, cudaEventDisableTiming);
    }

    const int SM128 = 3 * (128 * 128 + 128 * 128) + 256;   // 98560 bytes
    const int SM64  = 3 * (128 * 128 +  64 * 128) + 256;   // 73984 bytes
    cudaFuncSetAttribute(hgemm_kernel<128, true>,  cudaFuncAttributeMaxDynamicSharedMemorySize, SM128);
    cudaFuncSetAttribute(hgemm_kernel<128, false>, cudaFuncAttributeMaxDynamicSharedMemorySize, SM128);
    cudaFuncSetAttribute(hgemm_kernel<64,  true>,  cudaFuncAttributeMaxDynamicSharedMemorySize, SM64);

    const long SSl = SS, SSS = SSl * SSl;
    dim3 blk(256);
    dim3 gblk(128);
    dim3 tblk(32, 8);

    // 0) X -> half (both paths need it)
    f2h_kernel<<<(NTOK * (long)EE / 4 + 255) / 256, blk>>>(
        (const float4*)X, (__half2*)Xh, NTOK * (long)EE / 4);
    cudaEventRecord(evFork, 0);
    cudaStreamWaitEvent(side, evFork, 0);

    // ---- side stream: V path + weight transposes (independent of QK/scores) ----
    pack_w_kernel<<<dim3(2, 32, HH), tblk, 0, side>>>(WV, Wvt);
    hgemm_kernel<128, true><<<dim3(SS / 128, 1024 / 128, BB), gblk, SM128, side>>>(
        Wvt, Xh, Vth, EE, EE, EE, SS,
        0, 0, (long)SS * EE, 0, 1024L * SS, 0, 1, nullptr, nullptr, 0, 0, 0, nullptr);
    transpose_h_kernel<<<dim3(1024 / 32, 1024 / 32), tblk, 0, side>>>(WO, Wot, 1024, 1024);
    transpose_h_kernel<<<dim3(FF / 32, EE / 32), tblk, 0, side>>>(W1, W1t, EE, FF);
    transpose_h_kernel<<<dim3(EE / 32, FF / 32), tblk, 0, side>>>(W2, W2t, FF, EE);
    cudaEventRecord(evJoin, side);

    // ---- main stream: QK -> scores -> reduce ----
    pack_w_kernel<<<dim3(2, 32, HH), tblk>>>(WQ, Wqk);
    pack_w_kernel<<<dim3(2, 32, HH), tblk>>>(WK, Wqk + 1024L * EE);

    // 1) QK projection: [8192,1024] x [2048,1024]^T -> QKh [8192,2048] half
    hgemm_kernel<128, true><<<dim3(2048 / 128, NTOK / 128, 1), gblk, SM128>>>(
        Xh, Wqk, QKh, EE, EE, EE, 2048,
        0, 0, 0, 0, 0, 0, 1, nullptr, nullptr, 0, 0, 0, nullptr);

    // 3) scores + exp + partial col sums: Q[2048,64] x K[2048,64]^T -> att half
    hgemm_kernel<128, true><<<dim3(SS / 128, SS / 128, BB * HH), gblk, SM128>>>(
        QKh, QKh + 1024, ATT, DD, 2048, 2048, SS,
        SSl * 2048, 64, SSl * 2048, 64, (long)HH * SSS, SSS, HH,
        nullptr, nullptr, 0, 0, 1, PART);

    // 4) reduce partials -> inv = 0.125/sum
    reduce_inv_kernel<<<dim3(SS / 256, BB * HH), blk>>>(PART, INV);

    // join: vscale needs Vth (side) + INV (main)
    cudaStreamWaitEvent(0, evJoin, 0);
    vscale_kernel<<<(int)(((long)BB * 1024 * SS / 2 + 255) / 256), blk>>>(Vth, INV);

    // 5) AV: per (b,h): att[2048,2048] x Vt'[64,2048]^T -> AVh[b*S+s][h*64+d]
    hgemm_kernel<64, true><<<dim3(1, SS / 128, BB * HH), gblk, SM64>>>(
        ATT, Vth, AVh, SS, SS, SS, EE,
        (long)HH * SSS, SSS, 1024L * SS, 64L * SS, SSl * EE, 64, HH,
        nullptr, nullptr, 0, 0, 0, nullptr);

    // 6) WO: [8192,1024] x [1024,1024]^T + X -> Y fp32; LN -> VAf/VAh
    hgemm_kernel<128, false><<<dim3(EE / 128, NTOK / 128, 1), gblk, SM128>>>(
        AVh, Wot, Y, 1024, 1024, 1024, EE,
        0, 0, 0, 0, 0, 0, 1, nullptr, X, EE, 0, 0, nullptr);
    layernorm_kernel<<<NTOK, blk>>>(Y, gamma, beta, VAf, VAh);

    // 7) FFN1: [8192,1024] x [4096,1024]^T + b1, relu -> H1h half
    hgemm_kernel<128, true><<<dim3(FF / 128, NTOK / 128, 1), gblk, SM128>>>(
        VAh, W1t, H1h, EE, EE, EE, FF,
        0, 0, 0, 0, 0, 0, 1, b1, nullptr, 0, 1, 0, nullptr);

    // 8) FFN2: [8192,4096] x [1024,4096]^T + b2 + VAf -> Z fp32; LN -> out
    hgemm_kernel<128, false><<<dim3(EE / 128, NTOK / 128, 1), gblk, SM128>>>(
        H1h, W2t, Z, FF, FF, FF, EE,
        0, 0, 0, 0, 0, 0, 1, b2, VAf, EE, 0, 0, nullptr);
    layernorm_kernel<<<NTOK, blk>>>(Z, gamma, beta, out, nullptr);
}

// round 9
// speedup vs baseline: 7.6427x; 1.0043x over previous
#include <cuda_runtime.h>
#include <cuda_fp16.h>
#include <cstdint>

#define BB 4
#define SS 2048
#define EE 1024
#define HH 16
#define DD 64
#define FF 4096
#define LN_EPS 1e-5f
#define NTOK (BB*SS)
#define EXP_SHIFT 12.0f

// ---------------- scratch (device globals) ----------------
__device__ __half g_Xh[(long)NTOK*EE];
__device__ __half g_Wqk[2048L*EE];
__device__ __half g_Wvt[1024L*EE];
__device__ __half g_Wot[1024L*1024];
__device__ __half g_W1t[(long)FF*EE];
__device__ __half g_W2t[(long)EE*FF];
__device__ __half g_QKh[(long)NTOK*2048];
__device__ __half g_Vth[(long)BB*1024*SS];
__device__ __half g_att[268435456L];
__device__ float  g_part[64L*32*SS];
__device__ float  g_inv[(long)BB*HH*SS];
__device__ __half g_AVh[(long)NTOK*EE];
__device__ float  g_Y[(long)NTOK*EE];
__device__ float  g_VAf[(long)NTOK*EE];
__device__ __half g_VAh[(long)NTOK*EE];
__device__ __half g_H1h[(long)NTOK*FF];
__device__ float  g_Z[(long)NTOK*EE];

// ---------------- PTX helpers ----------------
__device__ __forceinline__ uint32_t smem_u32(const void* p) {
    uint32_t a;
    asm("{ .reg .u64 t; cvta.to.shared.u64 t, %1; cvt.u32.u64 %0, t; }" : "=r"(a) : "l"(p));
    return a;
}
__device__ __forceinline__ void cp16(uint32_t dst, const void* src) {
    asm volatile("cp.async.cg.shared.global [%0], [%1], 16;" :: "r"(dst), "l"(src));
}

// ---------------- HMMA f16 GEMM: C[M,N] = A[M,K] * B[N,K]^T ----------------
// BM=128, BK=64, 128 threads = 4 warps (2m x 2n), warp 64xWN.
// 3-stage cp.async pipeline; fragment double-buffering across ks steps.
template<int BN, bool OUT_HALF>
__global__ __launch_bounds__(128, 2)
void hgemm_kernel(const __half* __restrict__ A, const __half* __restrict__ B,
                  void* __restrict__ Cv, int K, int lda, int ldb, int ldc,
                  long sA1, long sA2, long sB1, long sB2, long sC1, long sC2, int Z2,
                  const float* __restrict__ bias, const float* __restrict__ residual,
                  int ldr, int do_relu, int do_exp, float* __restrict__ part)
{
    constexpr int BM = 128;
    constexpr int STG_A = BM * 128;
    constexpr int STG_B = BN * 128;
    constexpr int STG   = STG_A + STG_B;
    constexpr int WN = BN / 2;
    constexpr int MT = 4;
    constexpr int NT = WN / 8;

    extern __shared__ char smem_raw[];
    const uint32_t sb0   = smem_u32(smem_raw);
    const uint32_t sbase = (sb0 + 127u) & ~127u;

    const int tid  = threadIdx.x;
    const int lane = tid & 31;
    const int wid  = tid >> 5;
    const int wm   = (wid & 1) << 6;
    const int wn   = (wid >> 1) * WN;

    const int z  = blockIdx.z;
    const int z1 = z / Z2, z2 = z - z1 * Z2;
    A += z1 * sA1 + z2 * sA2;
    B += z1 * sB1 + z2 * sB2;
    const long coff = z1 * sC1 + z2 * sC2;
    const int m0 = blockIdx.y * BM;
    const int n0 = blockIdx.x * BN;

    float acc[MT][NT][4];
    #pragma unroll
    for (int i = 0; i < MT; i++)
        #pragma unroll
        for (int j = 0; j < NT; j++)
            #pragma unroll
            for (int k = 0; k < 4; k++) acc[i][j][k] = 0.0f;

    const int nK = K >> 6;

    auto load_stage = [&](int stg, int kt) {
        uint32_t sA = sbase + stg * STG;
        const char* Ab = (const char*)(A + (long)m0 * lda + kt * 64);
        #pragma unroll
        for (int idx = tid; idx < BM * 8; idx += 128) {
            int r = idx >> 3, c = (idx & 7) << 4;
            uint32_t off = (uint32_t)(r * 128 + c); off ^= (off >> 3) & 0x70;
            cp16(sA + off, Ab + (long)r * lda * 2 + c);
        }
        uint32_t sB = sbase + stg * STG + STG_A;
        const char* Bb = (const char*)(B + (long)n0 * ldb + kt * 64);
        #pragma unroll
        for (int idx = tid; idx < BN * 8; idx += 128) {
            int r = idx >> 3, c = (idx & 7) << 4;
            uint32_t off = (uint32_t)(r * 128 + c); off ^= (off >> 3) & 0x70;
            cp16(sB + off, Bb + (long)r * ldb * 2 + c);
        }
        asm volatile("cp.async.commit_group;" ::: "memory");
    };

    // fragment loaders (ks = 0..3 within a stage)
    uint32_t afrag[2][MT][4];
    uint32_t bfrag[2][NT][2];
    auto load_afrags = [&](uint32_t sA, int ks, int buf) {
        #pragma unroll
        for (int mt = 0; mt < MT; mt++) {
            int m = wm + (mt << 4) + (lane & 15);
            uint32_t off = (uint32_t)((m << 7) + (ks << 5) + ((lane >> 4) << 4));
            off ^= (off >> 3) & 0x70;
            asm volatile("ldmatrix.sync.aligned.m8n8.x4.shared.b16 {%0,%1,%2,%3}, [%4];"
                : "=r"(afrag[buf][mt][0]), "=r"(afrag[buf][mt][1]),
                  "=r"(afrag[buf][mt][2]), "=r"(afrag[buf][mt][3])
                : "r"(sA + off));
        }
    };
    auto load_bfrags = [&](uint32_t sB, int ks, int buf) {
        #pragma unroll
        for (int p = 0; p < NT / 2; p++) {
            int quad = lane >> 3;
            int n = wn + (p << 4) + ((quad & 2) << 2) + (lane & 7);
            uint32_t off = (uint32_t)((n << 7) + (ks << 5) + ((quad & 1) << 4));
            off ^= (off >> 3) & 0x70;
            asm volatile("ldmatrix.sync.aligned.m8n8.x4.shared.b16 {%0,%1,%2,%3}, [%4];"
                : "=r"(bfrag[buf][2*p][0]), "=r"(bfrag[buf][2*p][1]),
                  "=r"(bfrag[buf][2*p+1][0]), "=r"(bfrag[buf][2*p+1][1])
                : "r"(sB + off));
        }
    };
    auto mma_all = [&](int buf) {
        #pragma unroll
        for (int mt = 0; mt < MT; mt++)
            #pragma unroll
            for (int nt = 0; nt < NT; nt++)
                asm("mma.sync.aligned.m16n8k16.row.col.f32.f16.f16.f32 "
                    "{%0,%1,%2,%3}, {%4,%5,%6,%7}, {%8,%9}, {%0,%1,%2,%3};"
                    : "+f"(acc[mt][nt][0]), "+f"(acc[mt][nt][1]),
                      "+f"(acc[mt][nt][2]), "+f"(acc[mt][nt][3])
                    : "r"(afrag[buf][mt][0]), "r"(afrag[buf][mt][1]),
                      "r"(afrag[buf][mt][2]), "r"(afrag[buf][mt][3]),
                      "r"(bfrag[buf][nt][0]), "r"(bfrag[buf][nt][1]));
    };

    load_stage(0, 0);
    if (nK > 1) load_stage(1, 1);

    for (int i = 0; i < nK; i++) {
        if (i + 1 < nK) asm volatile("cp.async.wait_group 1;" ::: "memory");
        else            asm volatile("cp.async.wait_group 0;" ::: "memory");
        __syncthreads();
        if (i + 2 < nK) load_stage((i + 2) % 3, i + 2);

        const uint32_t sA = sbase + (i % 3) * STG;
        const uint32_t sB = sA + STG_A;

        load_afrags(sA, 0, 0);
        load_bfrags(sB, 0, 0);
        #pragma unroll
        for (int ks = 0; ks < 4; ks++) {
            if (ks < 3) {
                load_afrags(sA, ks + 1, (ks + 1) & 1);
                load_bfrags(sB, ks + 1, (ks + 1) & 1);
            }
            mma_all(ks & 1);
        }
    }

    // -------- epilogue --------
    const int mrow = lane >> 2;
    const int ncol = (lane & 3) << 1;
    float cs[NT][2];
    #pragma unroll
    for (int j = 0; j < NT; j++) { cs[j][0] = 0.0f; cs[j][1] = 0.0f; }

    #pragma unroll
    for (int mt = 0; mt < MT; mt++) {
        #pragma unroll
        for (int nt = 0; nt < NT; nt++) {
            long gm = m0 + wm + (mt << 4) + mrow;
            int  gn = n0 + wn + (nt << 3) + ncol;
            float v0 = acc[mt][nt][0], v1 = acc[mt][nt][1];
            float v2 = acc[mt][nt][2], v3 = acc[mt][nt][3];
            if (bias) {
                float b0 = bias[gn], b1 = bias[gn + 1];
                v0 += b0; v1 += b1; v2 += b0; v3 += b1;
            }
            if (residual) {
                const float2 r0 = *(const float2*)(residual + gm * ldr + gn);
                const float2 r1 = *(const float2*)(residual + (gm + 8) * ldr + gn);
                v0 += r0.x; v1 += r0.y; v2 += r1.x; v3 += r1.y;
            }
            if (do_relu) {
                v0 = fmaxf(v0, 0.0f); v1 = fmaxf(v1, 0.0f);
                v2 = fmaxf(v2, 0.0f); v3 = fmaxf(v3, 0.0f);
            }
            if (do_exp) {
                v0 = fminf(__expf(v0 - EXP_SHIFT), 60000.0f);
                v1 = fminf(__expf(v1 - EXP_SHIFT), 60000.0f);
                v2 = fminf(__expf(v2 - EXP_SHIFT), 60000.0f);
                v3 = fminf(__expf(v3 - EXP_SHIFT), 60000.0f);
                cs[nt][0] += v0 + v2;
                cs[nt][1] += v1 + v3;
            }
            if (OUT_HALF) {
                *(__half2*)((__half*)Cv + coff + gm * ldc + gn)       = __floats2half2_rn(v0, v1);
                *(__half2*)((__half*)Cv + coff + (gm + 8) * ldc + gn) = __floats2half2_rn(v2, v3);
            } else {
                *(float2*)((float*)Cv + coff + gm * ldc + gn)       = make_float2(v0, v1);
                *(float2*)((float*)Cv + coff + (gm + 8) * ldc + gn) = make_float2(v2, v3);
            }
        }
    }

    if (do_exp) {
        #pragma unroll
        for (int nt = 0; nt < NT; nt++) {
            float c0 = cs[nt][0], c1 = cs[nt][1];
            #pragma unroll
            for (int o = 4; o <= 16; o <<= 1) {
                c0 += __shfl_xor_sync(0xffffffffu, c0, o);
                c1 += __shfl_xor_sync(0xffffffffu, c1, o);
            }
            if ((lane >> 2) == 0) {
                int gn = n0 + wn + (nt << 3) + ncol;
                long idx = (((long)z * gridDim.y + blockIdx.y) * 2 + (wid & 1)) * SS + gn;
                part[idx]     = c0;
                part[idx + 1] = c1;
            }
        }
    }
}

// ---------------- conversion / packing kernels ----------------
__global__ __launch_bounds__(256) void f2h_kernel(const float4* __restrict__ s,
                                                  __half2* __restrict__ d, long n4) {
    long i = (long)blockIdx.x * 256 + threadIdx.x;
    if (i < n4) {
        float4 v = s[i];
        d[i * 2]     = __floats2half2_rn(v.x, v.y);
        d[i * 2 + 1] = __floats2half2_rn(v.z, v.w);
    }
}
__global__ __launch_bounds__(256) void pack_w_kernel(const float* __restrict__ W,
                                                     __half* __restrict__ dst) {
    __shared__ float tile[32][33];
    int h  = blockIdx.z;
    int eb = blockIdx.y * 32, db = blockIdx.x * 32;
    const float* Wh = W + (long)h * EE * DD;
    #pragma unroll
    for (int dy = 0; dy < 32; dy += 8)
        tile[threadIdx.y + dy][threadIdx.x] =
            Wh[(long)(eb + threadIdx.y + dy) * DD + db + threadIdx.x];
    __syncthreads();
    #pragma unroll
    for (int dy = 0; dy < 32; dy += 8)
        dst[(long)(h * DD + db + threadIdx.y + dy) * EE + eb + threadIdx.x] =
            __float2half(tile[threadIdx.x][threadIdx.y + dy]);
}
__global__ __launch_bounds__(256) void transpose_h_kernel(const float* __restrict__ src,
                                                          __half* __restrict__ dst,
                                                          int R, int C) {
    __shared__ float tile[32][33];
    int rb = blockIdx.y * 32, cb = blockIdx.x * 32;
    #pragma unroll
    for (int dy = 0; dy < 32; dy += 8)
        tile[threadIdx.y + dy][threadIdx.x] =
            src[(long)(rb + threadIdx.y + dy) * C + cb + threadIdx.x];
    __syncthreads();
    #pragma unroll
    for (int dy = 0; dy < 32; dy += 8)
        dst[(long)(cb + threadIdx.y + dy) * R + rb + threadIdx.x] =
            __float2half(tile[threadIdx.x][threadIdx.y + dy]);
}

// ---------------- reduce partial col sums -> inv = 0.125/sum ----------------
__global__ __launch_bounds__(256) void reduce_inv_kernel(const float* __restrict__ part,
                                                         float* __restrict__ inv) {
    long z = blockIdx.y;
    int  t = blockIdx.x * 256 + threadIdx.x;
    const float* p = part + (z * 32) * (long)SS + t;
    float s = 0.0f;
    #pragma unroll
    for (int j = 0; j < 32; j++) s += p[(long)j * SS];
    inv[z * (long)SS + t] = 0.125f / s;
}

// ---------------- scale Vth rows by inv ----------------
__global__ __launch_bounds__(256) void vscale_kernel(__half* __restrict__ v,
                                                     const float* __restrict__ inv) {
    long i2 = (long)blockIdx.x * 256 + threadIdx.x;
    long i  = i2 * 2;
    if (i >= (long)BB * 1024 * SS) return;
    int t  = (int)(i & (SS - 1));
    int hd = (int)((i >> 11) & 1023);
    int b  = (int)(i >> 21);
    const float* ip = inv + ((long)(b * HH + (hd >> 6))) * SS + t;
    __half2* p = (__half2*)(v + i);
    float2 f = __half22float2(*p);
    f.x *= ip[0]; f.y *= ip[1];
    *p = __floats2half2_rn(f.x, f.y);
}

// ---------------- layernorm (E=1024), optional half copy ----------------
__global__ __launch_bounds__(256)
void layernorm_kernel(const float* __restrict__ x, const float* __restrict__ gamma,
                      const float* __restrict__ beta, float* __restrict__ outf,
                      __half* __restrict__ outh) {
    long row = blockIdx.x;
    const float* p = x + row * (long)EE;
    const int tid = threadIdx.x, lane = tid & 31, warp = tid >> 5;

    float v[4]; float s = 0.0f;
    #pragma unroll
    for (int i = 0; i < 4; i++) { v[i] = p[tid + i * 256]; s += v[i]; }
    __shared__ float red1[8], red2[8];
    #pragma unroll
    for (int o = 16; o > 0; o >>= 1) s += __shfl_xor_sync(0xffffffffu, s, o);
    if (lane == 0) red1[warp] = s;
    __syncthreads();
    float tot = red1[0];
    #pragma unroll
    for (int i = 1; i < 8; i++) tot += red1[i];
    float mu = tot * (1.0f / EE);

    float q = 0.0f;
    #pragma unroll
    for (int i = 0; i < 4; i++) { float d = v[i] - mu; q += d * d; }
    #pragma unroll
    for (int o = 16; o > 0; o >>= 1) q += __shfl_xor_sync(0xffffffffu, q, o);
    if (lane == 0) red2[warp] = q;
    __syncthreads();
    float qt = red2[0];
    #pragma unroll
    for (int i = 1; i < 8; i++) qt += red2[i];
    float rstd = rsqrtf(qt * (1.0f / EE) + LN_EPS);

    #pragma unroll
    for (int i = 0; i < 4; i++) {
        int col = tid + i * 256;
        float y = (v[i] - mu) * rstd * gamma[col] + beta[col];
        outf[row * (long)EE + col] = y;
        if (outh) outh[row * (long)EE + col] = __float2half(y);
    }
}

// ---------------- launcher ----------------
extern "C" void kernel_launch(void* const* d_in, const int* in_sizes, int n_in,
                              void* d_out, int out_size)
{
    const float* X     = (const float*)d_in[0];
    const float* WQ    = (const float*)d_in[1];
    const float* WK    = (const float*)d_in[2];
    const float* WV    = (const float*)d_in[3];
    const float* WO    = (const float*)d_in[4];
    const float* gamma = (const float*)d_in[5];
    const float* beta  = (const float*)d_in[6];
    const float* W1    = (const float*)d_in[7];
    const float* b1    = (const float*)d_in[8];
    const float* W2    = (const float*)d_in[9];
    const float* b2    = (const float*)d_in[10];
    float* out = (float*)d_out;

    __half *Xh, *Wqk, *Wvt, *Wot, *W1t, *W2t, *QKh, *Vth, *ATT, *AVh, *VAh, *H1h;
    float *PART, *INV, *Y, *VAf, *Z;
    cudaGetSymbolAddress((void**)&Xh,  g_Xh);
    cudaGetSymbolAddress((void**)&Wqk, g_Wqk);
    cudaGetSymbolAddress((void**)&Wvt, g_Wvt);
    cudaGetSymbolAddress((void**)&Wot, g_Wot);
    cudaGetSymbolAddress((void**)&W1t, g_W1t);
    cudaGetSymbolAddress((void**)&W2t, g_W2t);
    cudaGetSymbolAddress((void**)&QKh, g_QKh);
    cudaGetSymbolAddress((void**)&Vth, g_Vth);
    cudaGetSymbolAddress((void**)&ATT, g_att);
    cudaGetSymbolAddress((void**)&PART, g_part);
    cudaGetSymbolAddress((void**)&INV, g_inv);
    cudaGetSymbolAddress((void**)&AVh, g_AVh);
    cudaGetSymbolAddress((void**)&Y,   g_Y);
    cudaGetSymbolAddress((void**)&VAf, g_VAf);
    cudaGetSymbolAddress((void**)&VAh, g_VAh);
    cudaGetSymbolAddress((void**)&H1h, g_H1h);
    cudaGetSymbolAddress((void**)&Z,   g_Z);

    static cudaStream_t side = nullptr;
    static cudaEvent_t evFork = nullptr, evJoin = nullptr;
    if (!side) {
        cudaStreamCreateWithFlags(&side, cudaStreamNonBlocking);
        cudaEventCreateWithFlags(&evFork, cudaEventDisableTiming);
        cudaEventCreateWithFlags(&evJoin, cudaEventDisableTiming);
    }

    const int SM128 = 3 * (128 * 128 + 128 * 128) + 256;
    const int SM64  = 3 * (128 * 128 +  64 * 128) + 256;
    cudaFuncSetAttribute(hgemm_kernel<128, true>,  cudaFuncAttributeMaxDynamicSharedMemorySize, SM128);
    cudaFuncSetAttribute(hgemm_kernel<128, false>, cudaFuncAttributeMaxDynamicSharedMemorySize, SM128);
    cudaFuncSetAttribute(hgemm_kernel<64,  true>,  cudaFuncAttributeMaxDynamicSharedMemorySize, SM64);

    const long SSl = SS, SSS = SSl * SSl;
    dim3 blk(256);
    dim3 gblk(128);
    dim3 tblk(32, 8);

    // 0) X -> half
    f2h_kernel<<<(NTOK * (long)EE / 4 + 255) / 256, blk>>>(
        (const float4*)X, (__half2*)Xh, NTOK * (long)EE / 4);
    cudaEventRecord(evFork, 0);
    cudaStreamWaitEvent(side, evFork, 0);

    // ---- side stream: V path + weight transposes ----
    pack_w_kernel<<<dim3(2, 32, HH), tblk, 0, side>>>(WV, Wvt);
    hgemm_kernel<128, true><<<dim3(SS / 128, 1024 / 128, BB), gblk, SM128, side>>>(
        Wvt, Xh, Vth, EE, EE, EE, SS,
        0, 0, (long)SS * EE, 0, 1024L * SS, 0, 1, nullptr, nullptr, 0, 0, 0, nullptr);
    transpose_h_kernel<<<dim3(1024 / 32, 1024 / 32), tblk, 0, side>>>(WO, Wot, 1024, 1024);
    transpose_h_kernel<<<dim3(FF / 32, EE / 32), tblk, 0, side>>>(W1, W1t, EE, FF);
    transpose_h_kernel<<<dim3(EE / 32, FF / 32), tblk, 0, side>>>(W2, W2t, FF, EE);
    cudaEventRecord(evJoin, side);

    // ---- main stream: QK -> scores -> reduce ----
    pack_w_kernel<<<dim3(2, 32, HH), tblk>>>(WQ, Wqk);
    pack_w_kernel<<<dim3(2, 32, HH), tblk>>>(WK, Wqk + 1024L * EE);

    hgemm_kernel<128, true><<<dim3(2048 / 128, NTOK / 128, 1), gblk, SM128>>>(
        Xh, Wqk, QKh, EE, EE, EE, 2048,
        0, 0, 0, 0, 0, 0, 1, nullptr, nullptr, 0, 0, 0, nullptr);

    hgemm_kernel<128, true><<<dim3(SS / 128, SS / 128, BB * HH), gblk, SM128>>>(
        QKh, QKh + 1024, ATT, DD, 2048, 2048, SS,
        SSl * 2048, 64, SSl * 2048, 64, (long)HH * SSS, SSS, HH,
        nullptr, nullptr, 0, 0, 1, PART);

    reduce_inv_kernel<<<dim3(SS / 256, BB * HH), blk>>>(PART, INV);

    cudaStreamWaitEvent(0, evJoin, 0);
    vscale_kernel<<<(int)(((long)BB * 1024 * SS / 2 + 255) / 256), blk>>>(Vth, INV);

    hgemm_kernel<64, true><<<dim3(1, SS / 128, BB * HH), gblk, SM64>>>(
        ATT, Vth, AVh, SS, SS, SS, EE,
        (long)HH * SSS, SSS, 1024L * SS, 64L * SS, SSl * EE, 64, HH,
        nullptr, nullptr, 0, 0, 0, nullptr);

    hgemm_kernel<128, false><<<dim3(EE / 128, NTOK / 128, 1), gblk, SM128>>>(
        AVh, Wot, Y, 1024, 1024, 1024, EE,
        0, 0, 0, 0, 0, 0, 1, nullptr, X, EE, 0, 0, nullptr);
    layernorm_kernel<<<NTOK, blk>>>(Y, gamma, beta, VAf, VAh);

    hgemm_kernel<128, true><<<dim3(FF / 128, NTOK / 128, 1), gblk, SM128>>>(
        VAh, W1t, H1h, EE, EE, EE, FF,
        0, 0, 0, 0, 0, 0, 1, b1, nullptr, 0, 1, 0, nullptr);

    hgemm_kernel<128, false><<<dim3(EE / 128, NTOK / 128, 1), gblk, SM128>>>(
        H1h, W2t, Z, FF, FF, FF, EE,
        0, 0, 0, 0, 0, 0, 1, b2, VAf, EE, 0, 0, nullptr);
    layernorm_kernel<<<NTOK, blk>>>(Z, gamma, beta, out, nullptr);
}